// round 12
// baseline (speedup 1.0000x reference)
#include <cuda_runtime.h>
#include <math.h>

#define FULL 0xFFFFFFFFu

#define CH_A 0.955f
#define CH_B 1.3693f
#define CH_INF 1e6f

#define RB 32            // rows per block
#define NB 16            // blocks per image (= warps per CTA)

// ---- device scratch (no allocation allowed) ----
__device__ float    g_u[16 * 512 * 512];   // pass-local rows / final pass-2 rows
__device__ float    g_F[16 * 512 * 512];   // pass-1 seed prefix term
__device__ float    g_S[16 * 512 * 512];   // pass-2 suffix term
__device__ unsigned g_mask[16 * 8192];     // raw target bitboard (for k_losses)
__device__ int      g_dmaxb[16];           // per-image max distance (float bits, >=0)
__device__ int      g_hasfg[16];
__device__ float    g_acc[50];

// ============================================================================
// Seeds + F builder (+ accumulator zeroing): one CTA per image, 512 threads.
// ============================================================================
__global__ void k_seedsF(const int* __restrict__ target) {
    extern __shared__ unsigned char smem_raw[];
    unsigned* maskb = (unsigned*)smem_raw;   // 8192 words
    unsigned* hdb   = maskb + 8192;          // later reused as carry table C
    unsigned* heb   = hdb + 8192;
    unsigned* bdb   = heb + 8192;

    const int img  = blockIdx.x;
    const int tid  = threadIdx.x;
    const int lane = tid & 31;
    const int warp = tid >> 5;
    const int* tg  = target + img * (512 * 512);

    if (tid < 50) g_acc[tid] = 0.0f;          // all CTAs write 0: benign race
    if (tid < 16) g_dmaxb[tid] = 0;

    // Phase A: int4 loads, nibble pack via segmented reduce
    const int rowsub  = tid >> 7;
    const int colbase = (warp & 3) * 128;
    const int col     = colbase + lane * 4;
    const int grp     = lane >> 3;
    const int sub     = lane & 7;
    const unsigned gm = 0xFFu << (grp * 8);
    unsigned anyfg = 0;
    #pragma unroll 4
    for (int it = 0; it < 128; ++it) {
        int row = it * 4 + rowsub;
        int4 v4 = *(const int4*)(tg + row * 512 + col);
        unsigned nib = (v4.x > 0 ? 1u : 0u) | (v4.y > 0 ? 2u : 0u)
                     | (v4.z > 0 ? 4u : 0u) | (v4.w > 0 ? 8u : 0u);
        anyfg |= nib;
        unsigned word = __reduce_or_sync(gm, nib << (sub * 4));
        if (sub == 0) maskb[row * 16 + (colbase >> 5) + grp] = word;
    }
    int has_fg = __syncthreads_or(anyfg != 0);

    // Phase B: horizontal dilate/erode; export raw mask board
    unsigned* gmk = g_mask + img * 8192;
    #pragma unroll
    for (int k = 0; k < 16; ++k) {
        int i = tid + k * 512;
        int w = i & 15;
        unsigned cw  = maskb[i];
        gmk[i] = cw;
        unsigned pw  = (w > 0)  ? maskb[i - 1] : 0u;
        unsigned nw_ = (w < 15) ? maskb[i + 1] : 0u;
        unsigned ld = (cw << 1) | (pw >> 31);
        unsigned rd = (cw >> 1) | (nw_ << 31);
        hdb[i] = cw | ld | rd;
        unsigned le = (cw << 1) | ((w == 0)  ? 1u          : (pw >> 31));
        unsigned re = (cw >> 1) | ((w == 15) ? 0x80000000u : (nw_ << 31));
        heb[i] = cw & le & re;
    }
    __syncthreads();

    // Phase C: vertical combine -> boundary
    unsigned anyb = 0;
    #pragma unroll
    for (int k = 0; k < 16; ++k) {
        int i = tid + k * 512;
        int r = i >> 4;
        unsigned dil = hdb[i];
        unsigned ero = heb[i];
        if (r > 0)   { dil |= hdb[i - 16]; ero &= heb[i - 16]; }
        if (r < 511) { dil |= hdb[i + 16]; ero &= heb[i + 16]; }
        unsigned bd = dil & ~ero;
        bdb[i] = bd;
        anyb |= bd;
    }
    int has_b = __syncthreads_or(anyb != 0);

    // Phase D: seed words -> maskb
    #pragma unroll
    for (int k = 0; k < 16; ++k) {
        int i = tid + k * 512;
        maskb[i] = has_b ? bdb[i] : ~maskb[i];
    }
    __syncthreads();

    // Phase E: per-row carry table (thread = row)
    int* C = (int*)hdb;
    {
        int cur = -1;
        #pragma unroll
        for (int w = 0; w < 16; ++w) {
            C[tid * 16 + w] = cur;
            unsigned word = maskb[tid * 16 + w];
            if (word) cur = w * 32 + 31 - __clz(word);
        }
    }
    __syncthreads();

    // Phase F: write F (float4-coalesced)
    float* Fimg = g_F + img * 262144;
    for (int qq = tid; qq < 65536; qq += 512) {
        int idx = qq * 4;
        int r = idx >> 9, j0 = idx & 511;
        int w = j0 >> 5;
        unsigned word = maskb[r * 16 + w];
        int carry = C[r * 16 + w];
        float4 o;
        #pragma unroll
        for (int e = 0; e < 4; ++e) {
            int j = j0 + e, b = j & 31;
            unsigned lb = word & (0xFFFFFFFFu >> (31 - b));
            int id = lb ? (w * 32 + 31 - __clz(lb)) : carry;
            (&o.x)[e] = (id >= 0) ? (-CH_A * (float)id) : CH_INF;
        }
        *(float4*)(Fimg + idx) = o;
    }
    if (tid == 0) g_hasfg[img] = has_fg;
}

static __device__ __forceinline__ void ldrow16(float* d, const float* p) {
    float4 a = *(const float4*)(p);
    float4 b = *(const float4*)(p + 4);
    float4 c = *(const float4*)(p + 8);
    float4 e = *(const float4*)(p + 12);
    d[0]=a.x; d[1]=a.y; d[2]=a.z; d[3]=a.w;
    d[4]=b.x; d[5]=b.y; d[6]=b.z; d[7]=b.w;
    d[8]=c.x; d[9]=c.y; d[10]=c.z; d[11]=c.w;
    d[12]=e.x; d[13]=e.y; d[14]=e.z; d[15]=e.w;
}
static __device__ __forceinline__ void strow16(float* p, const float* d) {
    *(float4*)(p)      = make_float4(d[0], d[1], d[2], d[3]);
    *(float4*)(p + 4)  = make_float4(d[4], d[5], d[6], d[7]);
    *(float4*)(p + 8)  = make_float4(d[8], d[9], d[10], d[11]);
    *(float4*)(p + 12) = make_float4(d[12], d[13], d[14], d[15]);
}

static __device__ __forceinline__ float pscan_min(float x, int lane) {
    #pragma unroll
    for (int o = 1; o < 32; o <<= 1) {
        float v = __shfl_up_sync(FULL, x, o);
        if (lane >= o) x = fminf(x, v);
    }
    return x;
}
static __device__ __forceinline__ float sscan_min(float x, int lane) {
    #pragma unroll
    for (int o = 1; o < 32; o <<= 1) {
        float v = __shfl_down_sync(FULL, x, o);
        if (lane + o < 32) x = fminf(x, v);
    }
    return x;
}

// Suffix-scan a fixed row into S: S[j] = min_{k>=j}(out[k] + c2[k]) (segment-wise + warp)
static __device__ __forceinline__ void emitS(float* Sp, const float* out, const float* c2, int lane) {
    float nxc[16], s[16];
    #pragma unroll
    for (int j = 0; j < 16; ++j) nxc[j] = out[j] + c2[j];
    s[15] = nxc[15];
    #pragma unroll
    for (int j = 14; j >= 0; --j) s[j] = fminf(s[j + 1], nxc[j]);
    float inc = sscan_min(s[0], lane);
    float exc = __shfl_down_sync(FULL, inc, 1);
    if (lane == 31) exc = CH_INF;
    #pragma unroll
    for (int k = 0; k < 4; ++k)
        *(float4*)(Sp + 4 * k) = make_float4(fminf(s[4*k], exc), fminf(s[4*k+1], exc),
                                             fminf(s[4*k+2], exc), fminf(s[4*k+3], exc));
}

// ============================================================================
// PASS 1 fused: one CTA per image, 512 threads (warp = block).
// local (F -> g_u) | sync | bnd (windowed scans, smem) | sync | fix + emit S.
// ============================================================================
__global__ void __launch_bounds__(512, 1) k_pass1() {
    __shared__ float sb_t[2][512], sb_s[2][512];
    __shared__ float bnd_s[NB][512];
    const int img = blockIdx.x;
    const int tid = threadIdx.x;
    const int lane = tid & 31, w = tid >> 5;
    float* uimg = g_u + img * 262144;
    const float* Fimg = g_F + img * 262144;
    float* Simg = g_S + img * 262144;
    const int c0 = lane * 16;

    // ---- local phase: warp w runs block w ----
    {
        const float* Fb = Fimg + w * RB * 512;
        float* ub = uimg + w * RB * 512;
        float u[16], f[16], fn[16], fn2[16], nu[16];
        #pragma unroll
        for (int j = 0; j < 16; ++j) u[j] = CH_INF;
        ldrow16(f,  Fb + c0);
        ldrow16(fn, Fb + 512 + c0);
        for (int r = 0; r < RB; ++r) {
            if (r < RB - 2) ldrow16(fn2, Fb + (r + 2) * 512 + c0);
            float uL = __shfl_up_sync(FULL, u[15], 1); if (lane == 0)  uL = CH_INF;
            float uR = __shfl_down_sync(FULL, u[0], 1); if (lane == 31) uR = CH_INF;
            #pragma unroll
            for (int j = 0; j < 16; ++j) {
                float left  = (j == 0)  ? uL : u[j - 1];
                float right = (j == 15) ? uR : u[j + 1];
                nu[j] = fminf(fminf(u[j] + CH_A, left + (CH_B - CH_A)),
                              fminf(right + (CH_B + CH_A), f[j]));
            }
            strow16(ub + r * 512 + c0, nu);
            #pragma unroll
            for (int j = 0; j < 16; ++j) { u[j] = nu[j]; f[j] = fn[j]; fn[j] = fn2[j]; }
        }
    }
    __syncthreads();

    // ---- bnd phase: all 512 threads, serial over blocks ----
    {
        const int j = tid;
        const float c1 = CH_B - CH_A, c2c = CH_B + CH_A;
        const float c1j = c1 * (float)j, c2j = c2c * (float)j;
        float bb = uimg[(RB - 1) * 512 + j];
        bnd_s[0][j] = bb;
        float loc = uimg[(2 * RB - 1) * 512 + j];
        for (int i = 1; i < NB; ++i) {
            float t = bb - c1j;
            float s = bb + c2j;
            float pre_t = pscan_min(t, lane);
            float suf_t = sscan_min(t, lane);
            float pre_s = pscan_min(s, lane);
            float suf_s = sscan_min(s, lane);
            int p = i & 1;
            sb_t[p][j] = suf_t;
            sb_s[p][j] = pre_s;
            float locn = (i + 1 < NB) ? uimg[((i + 1) * RB + RB - 1) * 512 + j] : 0.0f;
            __syncthreads();
            float suf_t_prev = (w > 0)  ? sb_t[p][j - 32] : CH_INF;
            float pre_s_next = (w < 15) ? sb_s[p][j + 32] : CH_INF;
            float wr = c1j + fminf(suf_t_prev, pre_t);
            float wl = fminf(suf_s, pre_s_next) - c2j;
            float nb = fminf(fminf(wr, wl) + CH_A * (float)RB, loc);
            bb = nb;
            bnd_s[i][j] = nb;
            loc = locn;
        }
    }
    __syncthreads();

    // ---- fix + S phase: warp w fixes block w, emits S rows ----
    {
        float c2[16];
        #pragma unroll
        for (int j = 0; j < 16; ++j) c2[j] = CH_A * (float)(2 * (c0 + j) - 511);
        float* ub = uimg + w * RB * 512;
        float* Sb = Simg + w * RB * 512;

        if (w == 0) {
            float out[16];
            #pragma unroll 2
            for (int r = 0; r < RB; ++r) {
                ldrow16(out, ub + r * 512 + c0);
                emitS(Sb + r * 512 + c0, out, c2, lane);
            }
        } else {
            float v[16], nv[16], loc[16], locn[16], locn2[16];
            #pragma unroll
            for (int j = 0; j < 16; ++j) v[j] = bnd_s[w - 1][c0 + j];
            ldrow16(loc,  ub + c0);
            ldrow16(locn, ub + 512 + c0);
            for (int r = 0; r < RB; ++r) {
                if (r < RB - 2) ldrow16(locn2, ub + (r + 2) * 512 + c0);
                float vL = __shfl_up_sync(FULL, v[15], 1); if (lane == 0)  vL = CH_INF;
                float vR = __shfl_down_sync(FULL, v[0], 1); if (lane == 31) vR = CH_INF;
                #pragma unroll
                for (int j = 0; j < 16; ++j) {
                    float left  = (j == 0)  ? vL : v[j - 1];
                    float right = (j == 15) ? vR : v[j + 1];
                    nv[j] = fminf(v[j] + CH_A, fminf(left + (CH_B - CH_A), right + (CH_B + CH_A)));
                }
                float out[16];
                #pragma unroll
                for (int j = 0; j < 16; ++j) out[j] = fminf(nv[j], loc[j]);
                emitS(Sb + r * 512 + c0, out, c2, lane);
                #pragma unroll
                for (int j = 0; j < 16; ++j) { v[j] = nv[j]; loc[j] = locn[j]; locn[j] = locn2[j]; }
            }
        }
    }
}

// ============================================================================
// PASS 2 fused (mirrored): local (S -> g_u) | bnd2 | fix + dmax.
// ============================================================================
__global__ void __launch_bounds__(512, 1) k_pass2() {
    __shared__ float sb_t[2][512], sb_s[2][512];
    __shared__ float bnd_s[NB][512];
    __shared__ float redmx[NB];
    const int img = blockIdx.x;
    const int tid = threadIdx.x;
    const int lane = tid & 31, w = tid >> 5;
    float* uimg = g_u + img * 262144;
    const float* Simg = g_S + img * 262144;
    const int c0 = lane * 16;

    // ---- local phase (bottom->top within block) ----
    {
        const float* Sb = Simg + w * RB * 512;
        float* ub = uimg + w * RB * 512;
        float u[16], f[16], fn[16], fn2[16], nu[16];
        #pragma unroll
        for (int j = 0; j < 16; ++j) u[j] = CH_INF;
        ldrow16(f,  Sb + (RB - 1) * 512 + c0);
        ldrow16(fn, Sb + (RB - 2) * 512 + c0);
        for (int r = RB - 1; r >= 0; --r) {
            if (r > 1) ldrow16(fn2, Sb + (r - 2) * 512 + c0);
            float uL = __shfl_up_sync(FULL, u[15], 1); if (lane == 0)  uL = CH_INF;
            float uR = __shfl_down_sync(FULL, u[0], 1); if (lane == 31) uR = CH_INF;
            #pragma unroll
            for (int j = 0; j < 16; ++j) {
                float left  = (j == 0)  ? uL : u[j - 1];
                float right = (j == 15) ? uR : u[j + 1];
                nu[j] = fminf(fminf(u[j] + CH_A, right + (CH_B - CH_A)),
                              fminf(left + (CH_B + CH_A), f[j]));
            }
            strow16(ub + r * 512 + c0, nu);
            #pragma unroll
            for (int j = 0; j < 16; ++j) { u[j] = nu[j]; f[j] = fn[j]; fn[j] = fn2[j]; }
        }
    }
    __syncthreads();

    // ---- bnd phase (mirrored; blocks bottom-up; boundary = first row of block) ----
    {
        const int j = tid;
        const float c1 = CH_B - CH_A, c2c = CH_B + CH_A;
        const float c1j = c1 * (float)j, c2j = c2c * (float)j;
        float bb = uimg[((NB - 1) * RB) * 512 + j];
        bnd_s[NB - 1][j] = bb;
        float loc = uimg[((NB - 2) * RB) * 512 + j];
        for (int i = NB - 2; i >= 0; --i) {
            float t = bb - c2j;
            float s = bb + c1j;
            float pre_t = pscan_min(t, lane);
            float suf_t = sscan_min(t, lane);
            float pre_s = pscan_min(s, lane);
            float suf_s = sscan_min(s, lane);
            int p = i & 1;
            sb_t[p][j] = suf_t;
            sb_s[p][j] = pre_s;
            float locn = (i > 0) ? uimg[((i - 1) * RB) * 512 + j] : 0.0f;
            __syncthreads();
            float suf_t_prev = (w > 0)  ? sb_t[p][j - 32] : CH_INF;
            float pre_s_next = (w < 15) ? sb_s[p][j + 32] : CH_INF;
            float wr = c2j + fminf(suf_t_prev, pre_t);
            float wl = fminf(suf_s, pre_s_next) - c1j;
            float nb = fminf(fminf(wr, wl) + CH_A * (float)RB, loc);
            bb = nb;
            bnd_s[i][j] = nb;
            loc = locn;
        }
    }
    __syncthreads();

    // ---- fix + dmax phase ----
    float dmx = 0.0f;
    {
        float co[16];
        #pragma unroll
        for (int j = 0; j < 16; ++j) co[j] = CH_A * (float)(511 - (c0 + j));
        float* ub = uimg + w * RB * 512;

        if (w == NB - 1) {
            float rr[16];
            #pragma unroll 2
            for (int r = 0; r < RB; ++r) {
                ldrow16(rr, ub + r * 512 + c0);
                #pragma unroll
                for (int j = 0; j < 16; ++j) dmx = fmaxf(dmx, rr[j] + co[j]);
            }
        } else {
            float v[16], nv[16], loc[16], locn[16], locn2[16];
            #pragma unroll
            for (int j = 0; j < 16; ++j) v[j] = bnd_s[w + 1][c0 + j];
            ldrow16(loc,  ub + (RB - 1) * 512 + c0);
            ldrow16(locn, ub + (RB - 2) * 512 + c0);
            for (int r = RB - 1; r >= 0; --r) {
                if (r > 1) ldrow16(locn2, ub + (r - 2) * 512 + c0);
                float vL = __shfl_up_sync(FULL, v[15], 1); if (lane == 0)  vL = CH_INF;
                float vR = __shfl_down_sync(FULL, v[0], 1); if (lane == 31) vR = CH_INF;
                #pragma unroll
                for (int j = 0; j < 16; ++j) {
                    float left  = (j == 0)  ? vL : v[j - 1];
                    float right = (j == 15) ? vR : v[j + 1];
                    nv[j] = fminf(v[j] + CH_A, fminf(right + (CH_B - CH_A), left + (CH_B + CH_A)));
                }
                float out[16];
                #pragma unroll
                for (int j = 0; j < 16; ++j) {
                    out[j] = fminf(nv[j], loc[j]);
                    dmx = fmaxf(dmx, out[j] + co[j]);
                }
                strow16(ub + r * 512 + c0, out);
                #pragma unroll
                for (int j = 0; j < 16; ++j) { v[j] = nv[j]; loc[j] = locn[j]; locn[j] = locn2[j]; }
            }
        }
    }
    #pragma unroll
    for (int o = 16; o >= 1; o >>= 1) dmx = fmaxf(dmx, __shfl_xor_sync(FULL, dmx, o));
    if (lane == 0) redmx[w] = dmx;
    __syncthreads();
    if (tid == 0) {
        float mm = redmx[0];
        #pragma unroll
        for (int k = 1; k < NB; ++k) mm = fmaxf(mm, redmx[k]);
        g_dmaxb[img] = __float_as_int(mm);
    }
}

// ============================================================================
// Elementwise losses (target bits from g_mask; untilts u2 on the fly).
// ============================================================================
__global__ void k_losses(const float* __restrict__ pred) {
    const int img   = blockIdx.x >> 7;
    const int chunk = blockIdx.x & 127;
    const int tid   = threadIdx.x;  // 256

    float mx  = __int_as_float(g_dmaxb[img]);
    float inv = (mx > 0.0f) ? (1.0f / fmaxf(mx, 1e-12f)) : 1.0f;
    int hfg   = g_hasfg[img];
    const unsigned* gmk = g_mask + img * 8192;

    float s_focal = 0.f, s_bnd = 0.f, s_i = 0.f, s_p = 0.f, s_t = 0.f;

    #pragma unroll
    for (int k = 0; k < 2; ++k) {
        int li = chunk * 2048 + (k * 256 + tid) * 4;
        int i  = img * 262144 + li;
        float4 x4 = *(const float4*)(pred + i);
        float4 u4 = *(const float4*)(g_u + i);
        unsigned bits = (gmk[li >> 5] >> (li & 31)) & 0xFu;
        int col = li & 511;
        #pragma unroll
        for (int e = 0; e < 4; ++e) {
            float x   = (&x4.x)[e];
            int   tgi = (bits >> e) & 1;
            float dd  = (&u4.x)[e] + CH_A * (float)(511 - col - e);
            float t = (float)tgi;
            float ax = fabsf(x);
            float ee = __expf(-ax);
            float l  = __logf(1.0f + ee);
            float lsp = (x >= 0.f) ? -l : (x - l);
            float lsn = (x >= 0.f) ? (-x - l) : -l;
            float bce = -(t * lsp + (1.f - t) * lsn);
            float r1 = __fdividef(1.0f, 1.0f + ee);
            float p = (x >= 0.f) ? r1 : ee * r1;
            float pt = tgi ? p : (1.f - p);
            float at = tgi ? 0.25f : 0.75f;
            float om = 1.f - pt;
            s_focal += at * om * om * bce;
            s_i += p * t;
            s_p += p;
            s_t += t;
            float dn = dd * inv;
            float dist = hfg ? dn : 1.0f;
            s_bnd += (t * (1.f - p) + (1.f - t) * p) * (1.f + dist);
        }
    }

    #pragma unroll
    for (int o = 16; o >= 1; o >>= 1) {
        s_focal += __shfl_xor_sync(FULL, s_focal, o);
        s_bnd   += __shfl_xor_sync(FULL, s_bnd, o);
        s_i     += __shfl_xor_sync(FULL, s_i, o);
        s_p     += __shfl_xor_sync(FULL, s_p, o);
        s_t     += __shfl_xor_sync(FULL, s_t, o);
    }
    __shared__ float red[8][5];
    int lane = tid & 31, wid = tid >> 5;
    if (lane == 0) { red[wid][0]=s_focal; red[wid][1]=s_bnd; red[wid][2]=s_i; red[wid][3]=s_p; red[wid][4]=s_t; }
    __syncthreads();
    if (tid == 0) {
        float a0=0,a1=0,a2=0,a3=0,a4=0;
        #pragma unroll
        for (int k = 0; k < 8; ++k) { a0+=red[k][0]; a1+=red[k][1]; a2+=red[k][2]; a3+=red[k][3]; a4+=red[k][4]; }
        atomicAdd(&g_acc[0], a0);
        atomicAdd(&g_acc[1], a1);
        atomicAdd(&g_acc[2 + img], a2);
        atomicAdd(&g_acc[18 + img], a3);
        atomicAdd(&g_acc[34 + img], a4);
    }
}

// ============================================================================
// Final combine
// ============================================================================
__global__ void k_final(const float* __restrict__ log_vars, float* __restrict__ out) {
    if (threadIdx.x != 0) return;
    const float N = 16.0f * 512.0f * 512.0f;
    float focal = g_acc[0] / N;
    float bnd   = g_acc[1] / N;
    float dsum = 0.f, isum = 0.f;
    #pragma unroll
    for (int b = 0; b < 16; ++b) {
        float I = g_acc[2 + b];
        float T = g_acc[18 + b] + g_acc[34 + b];
        dsum += (2.0f * I + 1e-6f) / (T + 1e-6f);
        isum += (I + 1e-6f) / (T - I + 1e-6f);
    }
    float dice = 1.0f - dsum / 16.0f;
    float iou  = 1.0f - isum / 16.0f;
    float lv0 = log_vars[0], lv1 = log_vars[1], lv2 = log_vars[2], lv3 = log_vars[3];
    float total = expf(-lv0) * focal + lv0
                + expf(-lv1) * dice  + lv1
                + expf(-lv2) * bnd   + lv2
                + expf(-lv3) * iou   + lv3;
    out[0] = total; out[1] = focal; out[2] = dice; out[3] = bnd; out[4] = iou;
}

extern "C" void kernel_launch(void* const* d_in, const int* in_sizes, int n_in,
                              void* d_out, int out_size) {
    const float* pred     = (const float*)d_in[0];
    const float* log_vars = (const float*)d_in[2];
    float* out = (float*)d_out;

    const size_t smem_seeds = 4 * 8192 * sizeof(unsigned);
    cudaFuncSetAttribute(k_seedsF, cudaFuncAttributeMaxDynamicSharedMemorySize, (int)smem_seeds);

    k_seedsF<<<16, 512, smem_seeds>>>((const int*)d_in[1]);
    k_pass1<<<16, 512>>>();
    k_pass2<<<16, 512>>>();
    k_losses<<<2048, 256>>>(pred);
    k_final<<<1, 32>>>(log_vars, out);
}

// round 13
// speedup vs baseline: 1.7855x; 1.7855x over previous
#include <cuda_runtime.h>
#include <math.h>

#define FULL 0xFFFFFFFFu

#define CH_A 0.955f
#define CH_B 1.3693f
#define CH_INF 1e6f

#define RB 16            // rows per block
#define NB 32            // blocks per image

// ---- device scratch (no allocation allowed) ----
__device__ float    g_u[16 * 512 * 512];   // pass-1 tilted rows, then pass-2 tilted rows
__device__ float    g_F[16 * 512 * 512];   // pass-1 seed prefix term
__device__ float    g_S[16 * 512 * 512];   // pass-2 suffix term
__device__ float    g_bnd[16 * NB * 512];  // corrected block-boundary rows
__device__ unsigned g_mask[16 * 8192];     // raw target bitboard (for k_losses)
__device__ int      g_dmaxb[16];           // per-image max distance (float bits, >=0)
__device__ int      g_hasfg[16];
__device__ float    g_acc[50];

// ============================================================================
// Seeds + F builder (+ accumulator zeroing): one CTA per image, 512 threads.
// ============================================================================
__global__ void k_seedsF(const int* __restrict__ target) {
    extern __shared__ unsigned char smem_raw[];
    unsigned* maskb = (unsigned*)smem_raw;   // 8192 words
    unsigned* hdb   = maskb + 8192;          // later reused as carry table C
    unsigned* heb   = hdb + 8192;
    unsigned* bdb   = heb + 8192;

    const int img  = blockIdx.x;
    const int tid  = threadIdx.x;
    const int lane = tid & 31;
    const int warp = tid >> 5;
    const int* tg  = target + img * (512 * 512);

    if (tid < 50) g_acc[tid] = 0.0f;          // all CTAs write 0: benign
    if (tid < 16) g_dmaxb[tid] = 0;

    // Phase A: int4 loads, nibble pack via segmented reduce
    const int rowsub  = tid >> 7;
    const int colbase = (warp & 3) * 128;
    const int col     = colbase + lane * 4;
    const int grp     = lane >> 3;
    const int sub     = lane & 7;
    const unsigned gm = 0xFFu << (grp * 8);
    unsigned anyfg = 0;
    #pragma unroll 4
    for (int it = 0; it < 128; ++it) {
        int row = it * 4 + rowsub;
        int4 v4 = *(const int4*)(tg + row * 512 + col);
        unsigned nib = (v4.x > 0 ? 1u : 0u) | (v4.y > 0 ? 2u : 0u)
                     | (v4.z > 0 ? 4u : 0u) | (v4.w > 0 ? 8u : 0u);
        anyfg |= nib;
        unsigned word = __reduce_or_sync(gm, nib << (sub * 4));
        if (sub == 0) maskb[row * 16 + (colbase >> 5) + grp] = word;
    }
    int has_fg = __syncthreads_or(anyfg != 0);

    // Phase B: horizontal dilate/erode; export raw mask board
    unsigned* gmk = g_mask + img * 8192;
    #pragma unroll
    for (int k = 0; k < 16; ++k) {
        int i = tid + k * 512;
        int w = i & 15;
        unsigned cw  = maskb[i];
        gmk[i] = cw;
        unsigned pw  = (w > 0)  ? maskb[i - 1] : 0u;
        unsigned nw_ = (w < 15) ? maskb[i + 1] : 0u;
        unsigned ld = (cw << 1) | (pw >> 31);
        unsigned rd = (cw >> 1) | (nw_ << 31);
        hdb[i] = cw | ld | rd;
        unsigned le = (cw << 1) | ((w == 0)  ? 1u          : (pw >> 31));
        unsigned re = (cw >> 1) | ((w == 15) ? 0x80000000u : (nw_ << 31));
        heb[i] = cw & le & re;
    }
    __syncthreads();

    // Phase C: vertical combine -> boundary
    unsigned anyb = 0;
    #pragma unroll
    for (int k = 0; k < 16; ++k) {
        int i = tid + k * 512;
        int r = i >> 4;
        unsigned dil = hdb[i];
        unsigned ero = heb[i];
        if (r > 0)   { dil |= hdb[i - 16]; ero &= heb[i - 16]; }
        if (r < 511) { dil |= hdb[i + 16]; ero &= heb[i + 16]; }
        unsigned bd = dil & ~ero;
        bdb[i] = bd;
        anyb |= bd;
    }
    int has_b = __syncthreads_or(anyb != 0);

    // Phase D: seed words -> maskb
    #pragma unroll
    for (int k = 0; k < 16; ++k) {
        int i = tid + k * 512;
        maskb[i] = has_b ? bdb[i] : ~maskb[i];
    }
    __syncthreads();

    // Phase E: per-row carry table (thread = row)
    int* C = (int*)hdb;
    {
        int cur = -1;
        #pragma unroll
        for (int w = 0; w < 16; ++w) {
            C[tid * 16 + w] = cur;
            unsigned word = maskb[tid * 16 + w];
            if (word) cur = w * 32 + 31 - __clz(word);
        }
    }
    __syncthreads();

    // Phase F: write F (float4-coalesced)
    float* Fimg = g_F + img * 262144;
    for (int qq = tid; qq < 65536; qq += 512) {
        int idx = qq * 4;
        int r = idx >> 9, j0 = idx & 511;
        int w = j0 >> 5;
        unsigned word = maskb[r * 16 + w];
        int carry = C[r * 16 + w];
        float4 o;
        #pragma unroll
        for (int e = 0; e < 4; ++e) {
            int j = j0 + e, b = j & 31;
            unsigned lb = word & (0xFFFFFFFFu >> (31 - b));
            int id = lb ? (w * 32 + 31 - __clz(lb)) : carry;
            (&o.x)[e] = (id >= 0) ? (-CH_A * (float)id) : CH_INF;
        }
        *(float4*)(Fimg + idx) = o;
    }
    if (tid == 0) g_hasfg[img] = has_fg;
}

static __device__ __forceinline__ void ldrow16(float* d, const float* p) {
    float4 a = *(const float4*)(p);
    float4 b = *(const float4*)(p + 4);
    float4 c = *(const float4*)(p + 8);
    float4 e = *(const float4*)(p + 12);
    d[0]=a.x; d[1]=a.y; d[2]=a.z; d[3]=a.w;
    d[4]=b.x; d[5]=b.y; d[6]=b.z; d[7]=b.w;
    d[8]=c.x; d[9]=c.y; d[10]=c.z; d[11]=c.w;
    d[12]=e.x; d[13]=e.y; d[14]=e.z; d[15]=e.w;
}
static __device__ __forceinline__ void strow16(float* p, const float* d) {
    *(float4*)(p)      = make_float4(d[0], d[1], d[2], d[3]);
    *(float4*)(p + 4)  = make_float4(d[4], d[5], d[6], d[7]);
    *(float4*)(p + 8)  = make_float4(d[8], d[9], d[10], d[11]);
    *(float4*)(p + 12) = make_float4(d[12], d[13], d[14], d[15]);
}

// 16-lane group scans (inclusive), matching window +-16 for RB=16
static __device__ __forceinline__ float pscan16(float x, int lane) {
    #pragma unroll
    for (int o = 1; o < 16; o <<= 1) {
        float v = __shfl_up_sync(FULL, x, o);
        if ((lane & 15) >= o) x = fminf(x, v);
    }
    return x;
}
static __device__ __forceinline__ float sscan16(float x, int lane) {
    #pragma unroll
    for (int o = 1; o < 16; o <<= 1) {
        float v = __shfl_down_sync(FULL, x, o);
        if ((lane & 15) + o < 16) x = fminf(x, v);
    }
    return x;
}
static __device__ __forceinline__ float sscan_min(float x, int lane) {
    #pragma unroll
    for (int o = 1; o < 32; o <<= 1) {
        float v = __shfl_down_sync(FULL, x, o);
        if (lane + o < 32) x = fminf(x, v);
    }
    return x;
}

// Suffix-scan a row into S: S[j] = min_{k>=j}(out[k] + c2[k])
static __device__ __forceinline__ void emitS(float* Sp, const float* out, const float* c2, int lane) {
    float nxc[16], s[16];
    #pragma unroll
    for (int j = 0; j < 16; ++j) nxc[j] = out[j] + c2[j];
    s[15] = nxc[15];
    #pragma unroll
    for (int j = 14; j >= 0; --j) s[j] = fminf(s[j + 1], nxc[j]);
    float inc = sscan_min(s[0], lane);
    float exc = __shfl_down_sync(FULL, inc, 1);
    if (lane == 31) exc = CH_INF;
    #pragma unroll
    for (int k = 0; k < 4; ++k)
        *(float4*)(Sp + 4 * k) = make_float4(fminf(s[4*k], exc), fminf(s[4*k+1], exc),
                                             fminf(s[4*k+2], exc), fminf(s[4*k+3], exc));
}

// ============================================================================
// Pass-1 local: 1 warp per (image, block). 16-row recurrence from u=INF.
// ============================================================================
__global__ void __launch_bounds__(32, 1) k_local1() {
    const int img = blockIdx.x >> 5, blk = blockIdx.x & 31;
    const int lane = threadIdx.x, c0 = lane * 16;
    const float* Fb = g_F + img * 262144 + blk * RB * 512;
    float* ub = g_u + img * 262144 + blk * RB * 512;

    float u[16], f[16], fn[16], fn2[16], nu[16];
    #pragma unroll
    for (int j = 0; j < 16; ++j) u[j] = CH_INF;
    ldrow16(f,  Fb + c0);
    ldrow16(fn, Fb + 512 + c0);

    for (int r = 0; r < RB; ++r) {
        if (r < RB - 2) ldrow16(fn2, Fb + (r + 2) * 512 + c0);
        float uL = __shfl_up_sync(FULL, u[15], 1); if (lane == 0)  uL = CH_INF;
        float uR = __shfl_down_sync(FULL, u[0], 1); if (lane == 31) uR = CH_INF;
        #pragma unroll
        for (int j = 0; j < 16; ++j) {
            float left  = (j == 0)  ? uL : u[j - 1];
            float right = (j == 15) ? uR : u[j + 1];
            nu[j] = fminf(fminf(u[j] + CH_A, left + (CH_B - CH_A)),
                          fminf(right + (CH_B + CH_A), f[j]));
        }
        strow16(ub + r * 512 + c0, nu);
        #pragma unroll
        for (int j = 0; j < 16; ++j) { u[j] = nu[j]; f[j] = fn[j]; fn[j] = fn2[j]; }
    }
}

// ============================================================================
// Pass-1 boundary: 512 threads/image, 31 serial steps. Window +-16 via
// 16-lane group scans; one barrier per step.
// ============================================================================
__global__ void k_bnd1() {
    __shared__ float sb_t[2][512], sb_s[2][512];
    const int img = blockIdx.x;
    const int j = threadIdx.x, lane = j & 31;
    const int g = j >> 4;                       // 16-lane group id (0..31)
    const float* base = g_u + img * 262144;
    float* gb = g_bnd + img * NB * 512;
    const float c1 = CH_B - CH_A, c2 = CH_B + CH_A;
    const float c1j = c1 * (float)j, c2j = c2 * (float)j;

    float bb = base[(RB - 1) * 512 + j];
    gb[j] = bb;
    float loc = base[(2 * RB - 1) * 512 + j];

    for (int i = 1; i < NB; ++i) {
        float t = bb - c1j;                  // k<j direction, cost c1*(j-k)
        float s = bb + c2j;                  // k>j direction, cost c2*(k-j)
        float pre_t = pscan16(t, lane);
        float suf_t = sscan16(t, lane);
        float pre_s = pscan16(s, lane);
        float suf_s = sscan16(s, lane);
        int p = i & 1;
        sb_t[p][j] = suf_t;
        sb_s[p][j] = pre_s;
        float locn = (i + 1 < NB) ? base[((i + 1) * RB + RB - 1) * 512 + j] : 0.0f;
        __syncthreads();
        float suf_t_prev = (g > 0)  ? sb_t[p][j - 16] : CH_INF;
        float pre_s_next = (g < 31) ? sb_s[p][j + 16] : CH_INF;
        float wr = c1j + fminf(suf_t_prev, pre_t);
        float wl = fminf(suf_s, pre_s_next) - c2j;
        float nb = fminf(fminf(wr, wl) + CH_A * (float)RB, loc);
        bb = nb;
        gb[i * 512 + j] = nb;
        loc = locn;
    }
}

// ============================================================================
// Pass-1 fix + emit S: 1 warp per (image, block). Block 0 emits S only.
// ============================================================================
__global__ void __launch_bounds__(32, 1) k_fix1S() {
    const int img = blockIdx.x >> 5, blk = blockIdx.x & 31;
    const int lane = threadIdx.x, c0 = lane * 16;
    float* ub = g_u + img * 262144 + blk * RB * 512;
    float* Sb = g_S + img * 262144 + blk * RB * 512;

    float c2[16];
    #pragma unroll
    for (int j = 0; j < 16; ++j) c2[j] = CH_A * (float)(2 * (c0 + j) - 511);

    if (blk == 0) {
        float out[16];
        #pragma unroll 2
        for (int r = 0; r < RB; ++r) {
            ldrow16(out, ub + r * 512 + c0);
            emitS(Sb + r * 512 + c0, out, c2, lane);
        }
        return;
    }

    float v[16], nv[16], loc[16], locn[16], locn2[16];
    ldrow16(v, g_bnd + (img * NB + blk - 1) * 512 + c0);
    ldrow16(loc,  ub + c0);
    ldrow16(locn, ub + 512 + c0);

    for (int r = 0; r < RB; ++r) {
        if (r < RB - 2) ldrow16(locn2, ub + (r + 2) * 512 + c0);
        float vL = __shfl_up_sync(FULL, v[15], 1); if (lane == 0)  vL = CH_INF;
        float vR = __shfl_down_sync(FULL, v[0], 1); if (lane == 31) vR = CH_INF;
        #pragma unroll
        for (int j = 0; j < 16; ++j) {
            float left  = (j == 0)  ? vL : v[j - 1];
            float right = (j == 15) ? vR : v[j + 1];
            nv[j] = fminf(v[j] + CH_A, fminf(left + (CH_B - CH_A), right + (CH_B + CH_A)));
        }
        float out[16];
        #pragma unroll
        for (int j = 0; j < 16; ++j) out[j] = fminf(nv[j], loc[j]);
        strow16(ub + r * 512 + c0, out);
        emitS(Sb + r * 512 + c0, out, c2, lane);
        #pragma unroll
        for (int j = 0; j < 16; ++j) { v[j] = nv[j]; loc[j] = locn[j]; locn[j] = locn2[j]; }
    }
}

// ============================================================================
// Pass-2 local (mirrored, bottom->top within block).
// ============================================================================
__global__ void __launch_bounds__(32, 1) k_local2() {
    const int img = blockIdx.x >> 5, blk = blockIdx.x & 31;
    const int lane = threadIdx.x, c0 = lane * 16;
    const float* Sb = g_S + img * 262144 + blk * RB * 512;
    float* ub = g_u + img * 262144 + blk * RB * 512;

    float u[16], f[16], fn[16], fn2[16], nu[16];
    #pragma unroll
    for (int j = 0; j < 16; ++j) u[j] = CH_INF;
    ldrow16(f,  Sb + (RB - 1) * 512 + c0);
    ldrow16(fn, Sb + (RB - 2) * 512 + c0);

    for (int r = RB - 1; r >= 0; --r) {
        if (r > 1) ldrow16(fn2, Sb + (r - 2) * 512 + c0);
        float uL = __shfl_up_sync(FULL, u[15], 1); if (lane == 0)  uL = CH_INF;
        float uR = __shfl_down_sync(FULL, u[0], 1); if (lane == 31) uR = CH_INF;
        #pragma unroll
        for (int j = 0; j < 16; ++j) {
            float left  = (j == 0)  ? uL : u[j - 1];
            float right = (j == 15) ? uR : u[j + 1];
            nu[j] = fminf(fminf(u[j] + CH_A, right + (CH_B - CH_A)),
                          fminf(left + (CH_B + CH_A), f[j]));
        }
        strow16(ub + r * 512 + c0, nu);
        #pragma unroll
        for (int j = 0; j < 16; ++j) { u[j] = nu[j]; f[j] = fn[j]; fn[j] = fn2[j]; }
    }
}

// ============================================================================
// Pass-2 boundary (mirrored slopes), 31 serial steps, group-16 scans.
// ============================================================================
__global__ void k_bnd2() {
    __shared__ float sb_t[2][512], sb_s[2][512];
    const int img = blockIdx.x;
    const int j = threadIdx.x, lane = j & 31;
    const int g = j >> 4;
    const float* base = g_u + img * 262144;
    float* gb = g_bnd + img * NB * 512;
    const float c1 = CH_B - CH_A, c2 = CH_B + CH_A;
    const float c1j = c1 * (float)j, c2j = c2 * (float)j;

    float bb = base[((NB - 1) * RB) * 512 + j];
    gb[(NB - 1) * 512 + j] = bb;
    float loc = base[((NB - 2) * RB) * 512 + j];

    for (int i = NB - 2; i >= 0; --i) {
        float t = bb - c2j;                  // k<j direction, cost c2*(j-k)
        float s = bb + c1j;                  // k>j direction, cost c1*(k-j)
        float pre_t = pscan16(t, lane);
        float suf_t = sscan16(t, lane);
        float pre_s = pscan16(s, lane);
        float suf_s = sscan16(s, lane);
        int p = i & 1;
        sb_t[p][j] = suf_t;
        sb_s[p][j] = pre_s;
        float locn = (i > 0) ? base[((i - 1) * RB) * 512 + j] : 0.0f;
        __syncthreads();
        float suf_t_prev = (g > 0)  ? sb_t[p][j - 16] : CH_INF;
        float pre_s_next = (g < 31) ? sb_s[p][j + 16] : CH_INF;
        float wr = c2j + fminf(suf_t_prev, pre_t);
        float wl = fminf(suf_s, pre_s_next) - c1j;
        float nb = fminf(fminf(wr, wl) + CH_A * (float)RB, loc);
        bb = nb;
        gb[i * 512 + j] = nb;
        loc = locn;
    }
}

// ============================================================================
// Pass-2 fix + dmax fold. Grid 16*NB: blk<NB-1 fixes rows, blk==NB-1 max-only.
// ============================================================================
__global__ void __launch_bounds__(32, 1) k_fix2() {
    const int img = blockIdx.x >> 5;
    const int blk = blockIdx.x & 31;
    const int lane = threadIdx.x, c0 = lane * 16;
    float* ub = g_u + img * 262144 + blk * RB * 512;

    float co[16];
    #pragma unroll
    for (int j = 0; j < 16; ++j) co[j] = CH_A * (float)(511 - (c0 + j));

    float dmx = 0.0f;
    if (blk == NB - 1) {
        float rr[16];
        #pragma unroll 2
        for (int r = 0; r < RB; ++r) {
            ldrow16(rr, ub + r * 512 + c0);
            #pragma unroll
            for (int j = 0; j < 16; ++j) dmx = fmaxf(dmx, rr[j] + co[j]);
        }
    } else {
        float v[16], nv[16], loc[16], locn[16], locn2[16];
        ldrow16(v, g_bnd + (img * NB + blk + 1) * 512 + c0);
        ldrow16(loc,  ub + (RB - 1) * 512 + c0);
        ldrow16(locn, ub + (RB - 2) * 512 + c0);

        for (int r = RB - 1; r >= 0; --r) {
            if (r > 1) ldrow16(locn2, ub + (r - 2) * 512 + c0);
            float vL = __shfl_up_sync(FULL, v[15], 1); if (lane == 0)  vL = CH_INF;
            float vR = __shfl_down_sync(FULL, v[0], 1); if (lane == 31) vR = CH_INF;
            #pragma unroll
            for (int j = 0; j < 16; ++j) {
                float left  = (j == 0)  ? vL : v[j - 1];
                float right = (j == 15) ? vR : v[j + 1];
                nv[j] = fminf(v[j] + CH_A, fminf(right + (CH_B - CH_A), left + (CH_B + CH_A)));
            }
            float out[16];
            #pragma unroll
            for (int j = 0; j < 16; ++j) {
                out[j] = fminf(nv[j], loc[j]);
                dmx = fmaxf(dmx, out[j] + co[j]);
            }
            strow16(ub + r * 512 + c0, out);
            #pragma unroll
            for (int j = 0; j < 16; ++j) { v[j] = nv[j]; loc[j] = locn[j]; locn[j] = locn2[j]; }
        }
    }

    #pragma unroll
    for (int o = 16; o >= 1; o >>= 1) dmx = fmaxf(dmx, __shfl_xor_sync(FULL, dmx, o));
    if (lane == 0) atomicMax(&g_dmaxb[img], __float_as_int(dmx));
}

// ============================================================================
// Elementwise losses (target bits from g_mask; untilts u2 on the fly).
// ============================================================================
__global__ void k_losses(const float* __restrict__ pred) {
    const int img   = blockIdx.x >> 7;
    const int chunk = blockIdx.x & 127;
    const int tid   = threadIdx.x;  // 256

    float mx  = __int_as_float(g_dmaxb[img]);
    float inv = (mx > 0.0f) ? (1.0f / fmaxf(mx, 1e-12f)) : 1.0f;
    int hfg   = g_hasfg[img];
    const unsigned* gmk = g_mask + img * 8192;

    float s_focal = 0.f, s_bnd = 0.f, s_i = 0.f, s_p = 0.f, s_t = 0.f;

    #pragma unroll
    for (int k = 0; k < 2; ++k) {
        int li = chunk * 2048 + (k * 256 + tid) * 4;
        int i  = img * 262144 + li;
        float4 x4 = *(const float4*)(pred + i);
        float4 u4 = *(const float4*)(g_u + i);
        unsigned bits = (gmk[li >> 5] >> (li & 31)) & 0xFu;
        int col = li & 511;
        #pragma unroll
        for (int e = 0; e < 4; ++e) {
            float x   = (&x4.x)[e];
            int   tgi = (bits >> e) & 1;
            float dd  = (&u4.x)[e] + CH_A * (float)(511 - col - e);
            float t = (float)tgi;
            float ax = fabsf(x);
            float ee = __expf(-ax);
            float l  = __logf(1.0f + ee);
            float lsp = (x >= 0.f) ? -l : (x - l);
            float lsn = (x >= 0.f) ? (-x - l) : -l;
            float bce = -(t * lsp + (1.f - t) * lsn);
            float r1 = __fdividef(1.0f, 1.0f + ee);
            float p = (x >= 0.f) ? r1 : ee * r1;
            float pt = tgi ? p : (1.f - p);
            float at = tgi ? 0.25f : 0.75f;
            float om = 1.f - pt;
            s_focal += at * om * om * bce;
            s_i += p * t;
            s_p += p;
            s_t += t;
            float dn = dd * inv;
            float dist = hfg ? dn : 1.0f;
            s_bnd += (t * (1.f - p) + (1.f - t) * p) * (1.f + dist);
        }
    }

    #pragma unroll
    for (int o = 16; o >= 1; o >>= 1) {
        s_focal += __shfl_xor_sync(FULL, s_focal, o);
        s_bnd   += __shfl_xor_sync(FULL, s_bnd, o);
        s_i     += __shfl_xor_sync(FULL, s_i, o);
        s_p     += __shfl_xor_sync(FULL, s_p, o);
        s_t     += __shfl_xor_sync(FULL, s_t, o);
    }
    __shared__ float red[8][5];
    int lane = tid & 31, wid = tid >> 5;
    if (lane == 0) { red[wid][0]=s_focal; red[wid][1]=s_bnd; red[wid][2]=s_i; red[wid][3]=s_p; red[wid][4]=s_t; }
    __syncthreads();
    if (tid == 0) {
        float a0=0,a1=0,a2=0,a3=0,a4=0;
        #pragma unroll
        for (int k = 0; k < 8; ++k) { a0+=red[k][0]; a1+=red[k][1]; a2+=red[k][2]; a3+=red[k][3]; a4+=red[k][4]; }
        atomicAdd(&g_acc[0], a0);
        atomicAdd(&g_acc[1], a1);
        atomicAdd(&g_acc[2 + img], a2);
        atomicAdd(&g_acc[18 + img], a3);
        atomicAdd(&g_acc[34 + img], a4);
    }
}

// ============================================================================
// Final combine
// ============================================================================
__global__ void k_final(const float* __restrict__ log_vars, float* __restrict__ out) {
    if (threadIdx.x != 0) return;
    const float N = 16.0f * 512.0f * 512.0f;
    float focal = g_acc[0] / N;
    float bnd   = g_acc[1] / N;
    float dsum = 0.f, isum = 0.f;
    #pragma unroll
    for (int b = 0; b < 16; ++b) {
        float I = g_acc[2 + b];
        float T = g_acc[18 + b] + g_acc[34 + b];
        dsum += (2.0f * I + 1e-6f) / (T + 1e-6f);
        isum += (I + 1e-6f) / (T - I + 1e-6f);
    }
    float dice = 1.0f - dsum / 16.0f;
    float iou  = 1.0f - isum / 16.0f;
    float lv0 = log_vars[0], lv1 = log_vars[1], lv2 = log_vars[2], lv3 = log_vars[3];
    float total = expf(-lv0) * focal + lv0
                + expf(-lv1) * dice  + lv1
                + expf(-lv2) * bnd   + lv2
                + expf(-lv3) * iou   + lv3;
    out[0] = total; out[1] = focal; out[2] = dice; out[3] = bnd; out[4] = iou;
}

extern "C" void kernel_launch(void* const* d_in, const int* in_sizes, int n_in,
                              void* d_out, int out_size) {
    const float* pred     = (const float*)d_in[0];
    const float* log_vars = (const float*)d_in[2];
    float* out = (float*)d_out;

    const size_t smem_seeds = 4 * 8192 * sizeof(unsigned);
    cudaFuncSetAttribute(k_seedsF, cudaFuncAttributeMaxDynamicSharedMemorySize, (int)smem_seeds);

    k_seedsF<<<16, 512, smem_seeds>>>((const int*)d_in[1]);
    k_local1<<<16 * NB, 32>>>();
    k_bnd1<<<16, 512>>>();
    k_fix1S<<<16 * NB, 32>>>();
    k_local2<<<16 * NB, 32>>>();
    k_bnd2<<<16, 512>>>();
    k_fix2<<<16 * NB, 32>>>();
    k_losses<<<2048, 256>>>(pred);
    k_final<<<1, 32>>>(log_vars, out);
}

// round 14
// speedup vs baseline: 2.0733x; 1.1612x over previous
#include <cuda_runtime.h>
#include <math.h>

#define FULL 0xFFFFFFFFu

#define CH_A 0.955f
#define CH_B 1.3693f
#define CH_INF 1e6f

#define RB 16            // rows per block
#define NB 32            // blocks per image

// ---- device scratch (no allocation allowed) ----
__device__ float    g_u[16 * 512 * 512];   // pass-1 local rows, then pass-2 rows
__device__ float    g_F[16 * 512 * 512];   // pass-1 seed prefix term
__device__ float    g_bnd[16 * NB * 512];  // corrected block-boundary rows
__device__ unsigned g_mask[16 * 8192];     // raw target bitboard (for k_losses)
__device__ int      g_dmaxb[16];           // per-image max distance (float bits)
__device__ int      g_hasfg[16];
__device__ float    g_acc[50];

// ============================================================================
// Seeds + F builder (+ accumulator zeroing): one CTA per image, 512 threads.
// ============================================================================
__global__ void k_seedsF(const int* __restrict__ target) {
    extern __shared__ unsigned char smem_raw[];
    unsigned* maskb = (unsigned*)smem_raw;   // 8192 words
    unsigned* hdb   = maskb + 8192;          // later reused as carry table C
    unsigned* heb   = hdb + 8192;
    unsigned* bdb   = heb + 8192;

    const int img  = blockIdx.x;
    const int tid  = threadIdx.x;
    const int lane = tid & 31;
    const int warp = tid >> 5;
    const int* tg  = target + img * (512 * 512);

    if (tid < 50) g_acc[tid] = 0.0f;          // all CTAs write 0: benign
    if (tid < 16) g_dmaxb[tid] = 0;

    // Phase A: int4 loads, nibble pack via segmented reduce
    const int rowsub  = tid >> 7;
    const int colbase = (warp & 3) * 128;
    const int col     = colbase + lane * 4;
    const int grp     = lane >> 3;
    const int sub     = lane & 7;
    const unsigned gm = 0xFFu << (grp * 8);
    unsigned anyfg = 0;
    #pragma unroll 8
    for (int it = 0; it < 128; ++it) {
        int row = it * 4 + rowsub;
        int4 v4 = *(const int4*)(tg + row * 512 + col);
        unsigned nib = (v4.x > 0 ? 1u : 0u) | (v4.y > 0 ? 2u : 0u)
                     | (v4.z > 0 ? 4u : 0u) | (v4.w > 0 ? 8u : 0u);
        anyfg |= nib;
        unsigned word = __reduce_or_sync(gm, nib << (sub * 4));
        if (sub == 0) maskb[row * 16 + (colbase >> 5) + grp] = word;
    }
    int has_fg = __syncthreads_or(anyfg != 0);

    // Phase B: horizontal dilate/erode; export raw mask board
    unsigned* gmk = g_mask + img * 8192;
    #pragma unroll
    for (int k = 0; k < 16; ++k) {
        int i = tid + k * 512;
        int w = i & 15;
        unsigned cw  = maskb[i];
        gmk[i] = cw;
        unsigned pw  = (w > 0)  ? maskb[i - 1] : 0u;
        unsigned nw_ = (w < 15) ? maskb[i + 1] : 0u;
        unsigned ld = (cw << 1) | (pw >> 31);
        unsigned rd = (cw >> 1) | (nw_ << 31);
        hdb[i] = cw | ld | rd;
        unsigned le = (cw << 1) | ((w == 0)  ? 1u          : (pw >> 31));
        unsigned re = (cw >> 1) | ((w == 15) ? 0x80000000u : (nw_ << 31));
        heb[i] = cw & le & re;
    }
    __syncthreads();

    // Phase C: vertical combine -> boundary
    unsigned anyb = 0;
    #pragma unroll
    for (int k = 0; k < 16; ++k) {
        int i = tid + k * 512;
        int r = i >> 4;
        unsigned dil = hdb[i];
        unsigned ero = heb[i];
        if (r > 0)   { dil |= hdb[i - 16]; ero &= heb[i - 16]; }
        if (r < 511) { dil |= hdb[i + 16]; ero &= heb[i + 16]; }
        unsigned bd = dil & ~ero;
        bdb[i] = bd;
        anyb |= bd;
    }
    int has_b = __syncthreads_or(anyb != 0);

    // Phase D: seed words -> maskb
    #pragma unroll
    for (int k = 0; k < 16; ++k) {
        int i = tid + k * 512;
        maskb[i] = has_b ? bdb[i] : ~maskb[i];
    }
    __syncthreads();

    // Phase E: per-row carry table (thread = row)
    int* C = (int*)hdb;
    {
        int cur = -1;
        #pragma unroll
        for (int w = 0; w < 16; ++w) {
            C[tid * 16 + w] = cur;
            unsigned word = maskb[tid * 16 + w];
            if (word) cur = w * 32 + 31 - __clz(word);
        }
    }
    __syncthreads();

    // Phase F: write F (float4-coalesced)
    float* Fimg = g_F + img * 262144;
    for (int qq = tid; qq < 65536; qq += 512) {
        int idx = qq * 4;
        int r = idx >> 9, j0 = idx & 511;
        int w = j0 >> 5;
        unsigned word = maskb[r * 16 + w];
        int carry = C[r * 16 + w];
        float4 o;
        #pragma unroll
        for (int e = 0; e < 4; ++e) {
            int j = j0 + e, b = j & 31;
            unsigned lb = word & (0xFFFFFFFFu >> (31 - b));
            int id = lb ? (w * 32 + 31 - __clz(lb)) : carry;
            (&o.x)[e] = (id >= 0) ? (-CH_A * (float)id) : CH_INF;
        }
        *(float4*)(Fimg + idx) = o;
    }
    if (tid == 0) g_hasfg[img] = has_fg;
}

static __device__ __forceinline__ void ldrow16(float* d, const float* p) {
    float4 a = *(const float4*)(p);
    float4 b = *(const float4*)(p + 4);
    float4 c = *(const float4*)(p + 8);
    float4 e = *(const float4*)(p + 12);
    d[0]=a.x; d[1]=a.y; d[2]=a.z; d[3]=a.w;
    d[4]=b.x; d[5]=b.y; d[6]=b.z; d[7]=b.w;
    d[8]=c.x; d[9]=c.y; d[10]=c.z; d[11]=c.w;
    d[12]=e.x; d[13]=e.y; d[14]=e.z; d[15]=e.w;
}
static __device__ __forceinline__ void strow16(float* p, const float* d) {
    *(float4*)(p)      = make_float4(d[0], d[1], d[2], d[3]);
    *(float4*)(p + 4)  = make_float4(d[4], d[5], d[6], d[7]);
    *(float4*)(p + 8)  = make_float4(d[8], d[9], d[10], d[11]);
    *(float4*)(p + 12) = make_float4(d[12], d[13], d[14], d[15]);
}

// 16-lane group scans (inclusive)
static __device__ __forceinline__ float pscan16(float x, int lane) {
    #pragma unroll
    for (int o = 1; o < 16; o <<= 1) {
        float v = __shfl_up_sync(FULL, x, o);
        if ((lane & 15) >= o) x = fminf(x, v);
    }
    return x;
}
static __device__ __forceinline__ float sscan16(float x, int lane) {
    #pragma unroll
    for (int o = 1; o < 16; o <<= 1) {
        float v = __shfl_down_sync(FULL, x, o);
        if ((lane & 15) + o < 16) x = fminf(x, v);
    }
    return x;
}
static __device__ __forceinline__ float sscan_min(float x, int lane) {
    #pragma unroll
    for (int o = 1; o < 32; o <<= 1) {
        float v = __shfl_down_sync(FULL, x, o);
        if (lane + o < 32) x = fminf(x, v);
    }
    return x;
}

// Suffix-scan a row into S (shared): S[j] = min_{k>=j}(out[k] + c2[k])
static __device__ __forceinline__ void emitS(float* Sp, const float* out, const float* c2, int lane) {
    float nxc[16], s[16];
    #pragma unroll
    for (int j = 0; j < 16; ++j) nxc[j] = out[j] + c2[j];
    s[15] = nxc[15];
    #pragma unroll
    for (int j = 14; j >= 0; --j) s[j] = fminf(s[j + 1], nxc[j]);
    float inc = sscan_min(s[0], lane);
    float exc = __shfl_down_sync(FULL, inc, 1);
    if (lane == 31) exc = CH_INF;
    #pragma unroll
    for (int k = 0; k < 4; ++k)
        *(float4*)(Sp + 4 * k) = make_float4(fminf(s[4*k], exc), fminf(s[4*k+1], exc),
                                             fminf(s[4*k+2], exc), fminf(s[4*k+3], exc));
}

// ============================================================================
// Pass-1 local: 1 warp per (image, block). 16-row recurrence from u=INF.
// ============================================================================
__global__ void __launch_bounds__(32, 1) k_local1() {
    const int img = blockIdx.x >> 5, blk = blockIdx.x & 31;
    const int lane = threadIdx.x, c0 = lane * 16;
    const float* Fb = g_F + img * 262144 + blk * RB * 512;
    float* ub = g_u + img * 262144 + blk * RB * 512;

    float u[16], f[16], fn[16], fn2[16], nu[16];
    #pragma unroll
    for (int j = 0; j < 16; ++j) u[j] = CH_INF;
    ldrow16(f,  Fb + c0);
    ldrow16(fn, Fb + 512 + c0);

    for (int r = 0; r < RB; ++r) {
        if (r < RB - 2) ldrow16(fn2, Fb + (r + 2) * 512 + c0);
        float uL = __shfl_up_sync(FULL, u[15], 1); if (lane == 0)  uL = CH_INF;
        float uR = __shfl_down_sync(FULL, u[0], 1); if (lane == 31) uR = CH_INF;
        #pragma unroll
        for (int j = 0; j < 16; ++j) {
            float left  = (j == 0)  ? uL : u[j - 1];
            float right = (j == 15) ? uR : u[j + 1];
            nu[j] = fminf(fminf(u[j] + CH_A, left + (CH_B - CH_A)),
                          fminf(right + (CH_B + CH_A), f[j]));
        }
        strow16(ub + r * 512 + c0, nu);
        #pragma unroll
        for (int j = 0; j < 16; ++j) { u[j] = nu[j]; f[j] = fn[j]; fn[j] = fn2[j]; }
    }
}

// ============================================================================
// Pass-1 boundary: 512 threads/image, 31 serial steps. Window +-16 via
// 16-lane group scans; one barrier per step.
// ============================================================================
__global__ void k_bnd1() {
    __shared__ float sb_t[2][512], sb_s[2][512];
    const int img = blockIdx.x;
    const int j = threadIdx.x, lane = j & 31;
    const int g = j >> 4;
    const float* base = g_u + img * 262144;
    float* gb = g_bnd + img * NB * 512;
    const float c1 = CH_B - CH_A, c2 = CH_B + CH_A;
    const float c1j = c1 * (float)j, c2j = c2 * (float)j;

    float bb = base[(RB - 1) * 512 + j];
    gb[j] = bb;
    float loc = base[(2 * RB - 1) * 512 + j];

    for (int i = 1; i < NB; ++i) {
        float t = bb - c1j;
        float s = bb + c2j;
        float pre_t = pscan16(t, lane);
        float suf_t = sscan16(t, lane);
        float pre_s = pscan16(s, lane);
        float suf_s = sscan16(s, lane);
        int p = i & 1;
        sb_t[p][j] = suf_t;
        sb_s[p][j] = pre_s;
        float locn = (i + 1 < NB) ? base[((i + 1) * RB + RB - 1) * 512 + j] : 0.0f;
        __syncthreads();
        float suf_t_prev = (g > 0)  ? sb_t[p][j - 16] : CH_INF;
        float pre_s_next = (g < 31) ? sb_s[p][j + 16] : CH_INF;
        float wr = c1j + fminf(suf_t_prev, pre_t);
        float wl = fminf(suf_s, pre_s_next) - c2j;
        float nb = fminf(fminf(wr, wl) + CH_A * (float)RB, loc);
        bb = nb;
        gb[i * 512 + j] = nb;
        loc = locn;
    }
}

// ============================================================================
// FUSED pass-1 fix + emit S (to smem) + pass-2 local: 1 warp per (image, block).
// Fixed u1 never touches global; S lives in 32 KB shared.
// ============================================================================
__global__ void __launch_bounds__(32) k_fix1L2() {
    __shared__ float Ss[RB][512];
    const int img = blockIdx.x >> 5, blk = blockIdx.x & 31;
    const int lane = threadIdx.x, c0 = lane * 16;
    float* ub = g_u + img * 262144 + blk * RB * 512;

    float c2[16];
    #pragma unroll
    for (int j = 0; j < 16; ++j) c2[j] = CH_A * (float)(2 * (c0 + j) - 511);

    // ---- fix phase (or pass-through for block 0) + emit S to shared ----
    if (blk == 0) {
        float out[16];
        #pragma unroll 2
        for (int r = 0; r < RB; ++r) {
            ldrow16(out, ub + r * 512 + c0);
            emitS(&Ss[r][c0], out, c2, lane);
        }
    } else {
        float v[16], nv[16], loc[16], locn[16], locn2[16];
        ldrow16(v, g_bnd + (img * NB + blk - 1) * 512 + c0);
        ldrow16(loc,  ub + c0);
        ldrow16(locn, ub + 512 + c0);
        for (int r = 0; r < RB; ++r) {
            if (r < RB - 2) ldrow16(locn2, ub + (r + 2) * 512 + c0);
            float vL = __shfl_up_sync(FULL, v[15], 1); if (lane == 0)  vL = CH_INF;
            float vR = __shfl_down_sync(FULL, v[0], 1); if (lane == 31) vR = CH_INF;
            #pragma unroll
            for (int j = 0; j < 16; ++j) {
                float left  = (j == 0)  ? vL : v[j - 1];
                float right = (j == 15) ? vR : v[j + 1];
                nv[j] = fminf(v[j] + CH_A, fminf(left + (CH_B - CH_A), right + (CH_B + CH_A)));
            }
            float out[16];
            #pragma unroll
            for (int j = 0; j < 16; ++j) out[j] = fminf(nv[j], loc[j]);
            emitS(&Ss[r][c0], out, c2, lane);
            #pragma unroll
            for (int j = 0; j < 16; ++j) { v[j] = nv[j]; loc[j] = locn[j]; locn[j] = locn2[j]; }
        }
    }
    __syncwarp();

    // ---- pass-2 local phase (bottom->top within block), S from shared ----
    {
        float u[16], f[16], nu[16];
        #pragma unroll
        for (int j = 0; j < 16; ++j) u[j] = CH_INF;
        for (int r = RB - 1; r >= 0; --r) {
            ldrow16(f, &Ss[r][c0]);
            float uL = __shfl_up_sync(FULL, u[15], 1); if (lane == 0)  uL = CH_INF;
            float uR = __shfl_down_sync(FULL, u[0], 1); if (lane == 31) uR = CH_INF;
            #pragma unroll
            for (int j = 0; j < 16; ++j) {
                float left  = (j == 0)  ? uL : u[j - 1];
                float right = (j == 15) ? uR : u[j + 1];
                nu[j] = fminf(fminf(u[j] + CH_A, right + (CH_B - CH_A)),
                              fminf(left + (CH_B + CH_A), f[j]));
            }
            strow16(ub + r * 512 + c0, nu);
            #pragma unroll
            for (int j = 0; j < 16; ++j) u[j] = nu[j];
        }
    }
}

// ============================================================================
// Pass-2 boundary (mirrored slopes), 31 serial steps, group-16 scans.
// ============================================================================
__global__ void k_bnd2() {
    __shared__ float sb_t[2][512], sb_s[2][512];
    const int img = blockIdx.x;
    const int j = threadIdx.x, lane = j & 31;
    const int g = j >> 4;
    const float* base = g_u + img * 262144;
    float* gb = g_bnd + img * NB * 512;
    const float c1 = CH_B - CH_A, c2 = CH_B + CH_A;
    const float c1j = c1 * (float)j, c2j = c2 * (float)j;

    float bb = base[((NB - 1) * RB) * 512 + j];
    gb[(NB - 1) * 512 + j] = bb;
    float loc = base[((NB - 2) * RB) * 512 + j];

    for (int i = NB - 2; i >= 0; --i) {
        float t = bb - c2j;
        float s = bb + c1j;
        float pre_t = pscan16(t, lane);
        float suf_t = sscan16(t, lane);
        float pre_s = pscan16(s, lane);
        float suf_s = sscan16(s, lane);
        int p = i & 1;
        sb_t[p][j] = suf_t;
        sb_s[p][j] = pre_s;
        float locn = (i > 0) ? base[((i - 1) * RB) * 512 + j] : 0.0f;
        __syncthreads();
        float suf_t_prev = (g > 0)  ? sb_t[p][j - 16] : CH_INF;
        float pre_s_next = (g < 31) ? sb_s[p][j + 16] : CH_INF;
        float wr = c2j + fminf(suf_t_prev, pre_t);
        float wl = fminf(suf_s, pre_s_next) - c1j;
        float nb = fminf(fminf(wr, wl) + CH_A * (float)RB, loc);
        bb = nb;
        gb[i * 512 + j] = nb;
        loc = locn;
    }
}

// ============================================================================
// Pass-2 fix + dmax fold. Grid 16*NB: blk<NB-1 fixes rows, blk==NB-1 max-only.
// ============================================================================
__global__ void __launch_bounds__(32, 1) k_fix2() {
    const int img = blockIdx.x >> 5;
    const int blk = blockIdx.x & 31;
    const int lane = threadIdx.x, c0 = lane * 16;
    float* ub = g_u + img * 262144 + blk * RB * 512;

    float co[16];
    #pragma unroll
    for (int j = 0; j < 16; ++j) co[j] = CH_A * (float)(511 - (c0 + j));

    float dmx = 0.0f;
    if (blk == NB - 1) {
        float rr[16];
        #pragma unroll 2
        for (int r = 0; r < RB; ++r) {
            ldrow16(rr, ub + r * 512 + c0);
            #pragma unroll
            for (int j = 0; j < 16; ++j) dmx = fmaxf(dmx, rr[j] + co[j]);
        }
    } else {
        float v[16], nv[16], loc[16], locn[16], locn2[16];
        ldrow16(v, g_bnd + (img * NB + blk + 1) * 512 + c0);
        ldrow16(loc,  ub + (RB - 1) * 512 + c0);
        ldrow16(locn, ub + (RB - 2) * 512 + c0);

        for (int r = RB - 1; r >= 0; --r) {
            if (r > 1) ldrow16(locn2, ub + (r - 2) * 512 + c0);
            float vL = __shfl_up_sync(FULL, v[15], 1); if (lane == 0)  vL = CH_INF;
            float vR = __shfl_down_sync(FULL, v[0], 1); if (lane == 31) vR = CH_INF;
            #pragma unroll
            for (int j = 0; j < 16; ++j) {
                float left  = (j == 0)  ? vL : v[j - 1];
                float right = (j == 15) ? vR : v[j + 1];
                nv[j] = fminf(v[j] + CH_A, fminf(right + (CH_B - CH_A), left + (CH_B + CH_A)));
            }
            float out[16];
            #pragma unroll
            for (int j = 0; j < 16; ++j) {
                out[j] = fminf(nv[j], loc[j]);
                dmx = fmaxf(dmx, out[j] + co[j]);
            }
            strow16(ub + r * 512 + c0, out);
            #pragma unroll
            for (int j = 0; j < 16; ++j) { v[j] = nv[j]; loc[j] = locn[j]; locn[j] = locn2[j]; }
        }
    }

    #pragma unroll
    for (int o = 16; o >= 1; o >>= 1) dmx = fmaxf(dmx, __shfl_xor_sync(FULL, dmx, o));
    if (lane == 0) atomicMax(&g_dmaxb[img], __float_as_int(dmx));
}

// ============================================================================
// Elementwise losses (target bits from g_mask; untilts u2 on the fly).
// Grid 1024: 4 iterations per thread for MLP.
// ============================================================================
__global__ void k_losses(const float* __restrict__ pred) {
    const int img   = blockIdx.x >> 6;
    const int chunk = blockIdx.x & 63;
    const int tid   = threadIdx.x;  // 256

    float mx  = __int_as_float(g_dmaxb[img]);
    float inv = (mx > 0.0f) ? (1.0f / fmaxf(mx, 1e-12f)) : 1.0f;
    int hfg   = g_hasfg[img];
    const unsigned* gmk = g_mask + img * 8192;

    float s_focal = 0.f, s_bnd = 0.f, s_i = 0.f, s_p = 0.f, s_t = 0.f;

    #pragma unroll
    for (int k = 0; k < 4; ++k) {
        int li = chunk * 4096 + (k * 256 + tid) * 4;
        int i  = img * 262144 + li;
        float4 x4 = *(const float4*)(pred + i);
        float4 u4 = *(const float4*)(g_u + i);
        unsigned bits = (gmk[li >> 5] >> (li & 31)) & 0xFu;
        int col = li & 511;
        #pragma unroll
        for (int e = 0; e < 4; ++e) {
            float x   = (&x4.x)[e];
            int   tgi = (bits >> e) & 1;
            float dd  = (&u4.x)[e] + CH_A * (float)(511 - col - e);
            float t = (float)tgi;
            float ax = fabsf(x);
            float ee = __expf(-ax);
            float l  = __logf(1.0f + ee);
            float lsp = (x >= 0.f) ? -l : (x - l);
            float lsn = (x >= 0.f) ? (-x - l) : -l;
            float bce = -(t * lsp + (1.f - t) * lsn);
            float r1 = __fdividef(1.0f, 1.0f + ee);
            float p = (x >= 0.f) ? r1 : ee * r1;
            float pt = tgi ? p : (1.f - p);
            float at = tgi ? 0.25f : 0.75f;
            float om = 1.f - pt;
            s_focal += at * om * om * bce;
            s_i += p * t;
            s_p += p;
            s_t += t;
            float dn = dd * inv;
            float dist = hfg ? dn : 1.0f;
            s_bnd += (t * (1.f - p) + (1.f - t) * p) * (1.f + dist);
        }
    }

    #pragma unroll
    for (int o = 16; o >= 1; o >>= 1) {
        s_focal += __shfl_xor_sync(FULL, s_focal, o);
        s_bnd   += __shfl_xor_sync(FULL, s_bnd, o);
        s_i     += __shfl_xor_sync(FULL, s_i, o);
        s_p     += __shfl_xor_sync(FULL, s_p, o);
        s_t     += __shfl_xor_sync(FULL, s_t, o);
    }
    __shared__ float red[8][5];
    int lane = tid & 31, wid = tid >> 5;
    if (lane == 0) { red[wid][0]=s_focal; red[wid][1]=s_bnd; red[wid][2]=s_i; red[wid][3]=s_p; red[wid][4]=s_t; }
    __syncthreads();
    if (tid == 0) {
        float a0=0,a1=0,a2=0,a3=0,a4=0;
        #pragma unroll
        for (int k = 0; k < 8; ++k) { a0+=red[k][0]; a1+=red[k][1]; a2+=red[k][2]; a3+=red[k][3]; a4+=red[k][4]; }
        atomicAdd(&g_acc[0], a0);
        atomicAdd(&g_acc[1], a1);
        atomicAdd(&g_acc[2 + img], a2);
        atomicAdd(&g_acc[18 + img], a3);
        atomicAdd(&g_acc[34 + img], a4);
    }
}

// ============================================================================
// Final combine
// ============================================================================
__global__ void k_final(const float* __restrict__ log_vars, float* __restrict__ out) {
    if (threadIdx.x != 0) return;
    const float N = 16.0f * 512.0f * 512.0f;
    float focal = g_acc[0] / N;
    float bnd   = g_acc[1] / N;
    float dsum = 0.f, isum = 0.f;
    #pragma unroll
    for (int b = 0; b < 16; ++b) {
        float I = g_acc[2 + b];
        float T = g_acc[18 + b] + g_acc[34 + b];
        dsum += (2.0f * I + 1e-6f) / (T + 1e-6f);
        isum += (I + 1e-6f) / (T - I + 1e-6f);
    }
    float dice = 1.0f - dsum / 16.0f;
    float iou  = 1.0f - isum / 16.0f;
    float lv0 = log_vars[0], lv1 = log_vars[1], lv2 = log_vars[2], lv3 = log_vars[3];
    float total = expf(-lv0) * focal + lv0
                + expf(-lv1) * dice  + lv1
                + expf(-lv2) * bnd   + lv2
                + expf(-lv3) * iou   + lv3;
    out[0] = total; out[1] = focal; out[2] = dice; out[3] = bnd; out[4] = iou;
}

extern "C" void kernel_launch(void* const* d_in, const int* in_sizes, int n_in,
                              void* d_out, int out_size) {
    const float* pred     = (const float*)d_in[0];
    const float* log_vars = (const float*)d_in[2];
    float* out = (float*)d_out;

    const size_t smem_seeds = 4 * 8192 * sizeof(unsigned);
    cudaFuncSetAttribute(k_seedsF, cudaFuncAttributeMaxDynamicSharedMemorySize, (int)smem_seeds);

    k_seedsF<<<16, 512, smem_seeds>>>((const int*)d_in[1]);
    k_local1<<<16 * NB, 32>>>();
    k_bnd1<<<16, 512>>>();
    k_fix1L2<<<16 * NB, 32>>>();
    k_bnd2<<<16, 512>>>();
    k_fix2<<<16 * NB, 32>>>();
    k_losses<<<1024, 256>>>(pred);
    k_final<<<1, 32>>>(log_vars, out);
}

// round 15
// speedup vs baseline: 2.1007x; 1.0132x over previous
#include <cuda_runtime.h>
#include <math.h>

#define FULL 0xFFFFFFFFu

#define CH_A 0.955f
#define CH_B 1.3693f
#define CH_INF 1e6f

#define RB 16            // rows per block
#define NB 32            // blocks per image

// ---- device scratch (no allocation allowed) ----
__device__ float    g_u[16 * 512 * 512];   // pass-1 local rows, then pass-2 rows
__device__ float    g_F[16 * 512 * 512];   // pass-1 seed prefix term
__device__ float    g_bnd[16 * NB * 512];  // corrected block-boundary rows
__device__ unsigned g_mask[16 * 8192];     // raw target bitboard
__device__ int      g_dmaxb[16];           // per-image max distance (float bits)
__device__ int      g_hasfg[16];
// [0]=focal | [2..17]=inter | [18..33]=psum | [34..49]=tsum | [50..65]=S1 | [66..81]=S2
__device__ float    g_acc[82];

// ============================================================================
// Seeds + F builder (+ accumulator zeroing): one CTA per image, 512 threads.
// ============================================================================
__global__ void k_seedsF(const int* __restrict__ target) {
    extern __shared__ unsigned char smem_raw[];
    unsigned* maskb = (unsigned*)smem_raw;   // 8192 words
    unsigned* hdb   = maskb + 8192;          // later reused as carry table C
    unsigned* heb   = hdb + 8192;
    unsigned* bdb   = heb + 8192;

    const int img  = blockIdx.x;
    const int tid  = threadIdx.x;
    const int lane = tid & 31;
    const int warp = tid >> 5;
    const int* tg  = target + img * (512 * 512);

    if (tid < 82) g_acc[tid] = 0.0f;          // all CTAs write 0: benign
    if (tid < 16) g_dmaxb[tid] = 0;

    // Phase A: int4 loads, nibble pack via segmented reduce
    const int rowsub  = tid >> 7;
    const int colbase = (warp & 3) * 128;
    const int col     = colbase + lane * 4;
    const int grp     = lane >> 3;
    const int sub     = lane & 7;
    const unsigned gm = 0xFFu << (grp * 8);
    unsigned anyfg = 0;
    #pragma unroll 8
    for (int it = 0; it < 128; ++it) {
        int row = it * 4 + rowsub;
        int4 v4 = *(const int4*)(tg + row * 512 + col);
        unsigned nib = (v4.x > 0 ? 1u : 0u) | (v4.y > 0 ? 2u : 0u)
                     | (v4.z > 0 ? 4u : 0u) | (v4.w > 0 ? 8u : 0u);
        anyfg |= nib;
        unsigned word = __reduce_or_sync(gm, nib << (sub * 4));
        if (sub == 0) maskb[row * 16 + (colbase >> 5) + grp] = word;
    }
    int has_fg = __syncthreads_or(anyfg != 0);

    // Phase B: horizontal dilate/erode; export raw mask board
    unsigned* gmk = g_mask + img * 8192;
    #pragma unroll
    for (int k = 0; k < 16; ++k) {
        int i = tid + k * 512;
        int w = i & 15;
        unsigned cw  = maskb[i];
        gmk[i] = cw;
        unsigned pw  = (w > 0)  ? maskb[i - 1] : 0u;
        unsigned nw_ = (w < 15) ? maskb[i + 1] : 0u;
        unsigned ld = (cw << 1) | (pw >> 31);
        unsigned rd = (cw >> 1) | (nw_ << 31);
        hdb[i] = cw | ld | rd;
        unsigned le = (cw << 1) | ((w == 0)  ? 1u          : (pw >> 31));
        unsigned re = (cw >> 1) | ((w == 15) ? 0x80000000u : (nw_ << 31));
        heb[i] = cw & le & re;
    }
    __syncthreads();

    // Phase C: vertical combine -> boundary
    unsigned anyb = 0;
    #pragma unroll
    for (int k = 0; k < 16; ++k) {
        int i = tid + k * 512;
        int r = i >> 4;
        unsigned dil = hdb[i];
        unsigned ero = heb[i];
        if (r > 0)   { dil |= hdb[i - 16]; ero &= heb[i - 16]; }
        if (r < 511) { dil |= hdb[i + 16]; ero &= heb[i + 16]; }
        unsigned bd = dil & ~ero;
        bdb[i] = bd;
        anyb |= bd;
    }
    int has_b = __syncthreads_or(anyb != 0);

    // Phase D: seed words -> maskb
    #pragma unroll
    for (int k = 0; k < 16; ++k) {
        int i = tid + k * 512;
        maskb[i] = has_b ? bdb[i] : ~maskb[i];
    }
    __syncthreads();

    // Phase E: per-row carry table (thread = row)
    int* C = (int*)hdb;
    {
        int cur = -1;
        #pragma unroll
        for (int w = 0; w < 16; ++w) {
            C[tid * 16 + w] = cur;
            unsigned word = maskb[tid * 16 + w];
            if (word) cur = w * 32 + 31 - __clz(word);
        }
    }
    __syncthreads();

    // Phase F: write F (float4-coalesced)
    float* Fimg = g_F + img * 262144;
    for (int qq = tid; qq < 65536; qq += 512) {
        int idx = qq * 4;
        int r = idx >> 9, j0 = idx & 511;
        int w = j0 >> 5;
        unsigned word = maskb[r * 16 + w];
        int carry = C[r * 16 + w];
        float4 o;
        #pragma unroll
        for (int e = 0; e < 4; ++e) {
            int j = j0 + e, b = j & 31;
            unsigned lb = word & (0xFFFFFFFFu >> (31 - b));
            int id = lb ? (w * 32 + 31 - __clz(lb)) : carry;
            (&o.x)[e] = (id >= 0) ? (-CH_A * (float)id) : CH_INF;
        }
        *(float4*)(Fimg + idx) = o;
    }
    if (tid == 0) g_hasfg[img] = has_fg;
}

static __device__ __forceinline__ void ldrow16(float* d, const float* p) {
    float4 a = *(const float4*)(p);
    float4 b = *(const float4*)(p + 4);
    float4 c = *(const float4*)(p + 8);
    float4 e = *(const float4*)(p + 12);
    d[0]=a.x; d[1]=a.y; d[2]=a.z; d[3]=a.w;
    d[4]=b.x; d[5]=b.y; d[6]=b.z; d[7]=b.w;
    d[8]=c.x; d[9]=c.y; d[10]=c.z; d[11]=c.w;
    d[12]=e.x; d[13]=e.y; d[14]=e.z; d[15]=e.w;
}
static __device__ __forceinline__ void strow16(float* p, const float* d) {
    *(float4*)(p)      = make_float4(d[0], d[1], d[2], d[3]);
    *(float4*)(p + 4)  = make_float4(d[4], d[5], d[6], d[7]);
    *(float4*)(p + 8)  = make_float4(d[8], d[9], d[10], d[11]);
    *(float4*)(p + 12) = make_float4(d[12], d[13], d[14], d[15]);
}

// 16-lane group scans (inclusive)
static __device__ __forceinline__ float pscan16(float x, int lane) {
    #pragma unroll
    for (int o = 1; o < 16; o <<= 1) {
        float v = __shfl_up_sync(FULL, x, o);
        if ((lane & 15) >= o) x = fminf(x, v);
    }
    return x;
}
static __device__ __forceinline__ float sscan16(float x, int lane) {
    #pragma unroll
    for (int o = 1; o < 16; o <<= 1) {
        float v = __shfl_down_sync(FULL, x, o);
        if ((lane & 15) + o < 16) x = fminf(x, v);
    }
    return x;
}
static __device__ __forceinline__ float sscan_min(float x, int lane) {
    #pragma unroll
    for (int o = 1; o < 32; o <<= 1) {
        float v = __shfl_down_sync(FULL, x, o);
        if (lane + o < 32) x = fminf(x, v);
    }
    return x;
}

// Suffix-scan a row into S (shared): S[j] = min_{k>=j}(out[k] + c2[k])
static __device__ __forceinline__ void emitS(float* Sp, const float* out, const float* c2, int lane) {
    float nxc[16], s[16];
    #pragma unroll
    for (int j = 0; j < 16; ++j) nxc[j] = out[j] + c2[j];
    s[15] = nxc[15];
    #pragma unroll
    for (int j = 14; j >= 0; --j) s[j] = fminf(s[j + 1], nxc[j]);
    float inc = sscan_min(s[0], lane);
    float exc = __shfl_down_sync(FULL, inc, 1);
    if (lane == 31) exc = CH_INF;
    #pragma unroll
    for (int k = 0; k < 4; ++k)
        *(float4*)(Sp + 4 * k) = make_float4(fminf(s[4*k], exc), fminf(s[4*k+1], exc),
                                             fminf(s[4*k+2], exc), fminf(s[4*k+3], exc));
}

// ============================================================================
// Pass-1 local: 1 warp per (image, block). 16-row recurrence from u=INF.
// ============================================================================
__global__ void __launch_bounds__(32, 1) k_local1() {
    const int img = blockIdx.x >> 5, blk = blockIdx.x & 31;
    const int lane = threadIdx.x, c0 = lane * 16;
    const float* Fb = g_F + img * 262144 + blk * RB * 512;
    float* ub = g_u + img * 262144 + blk * RB * 512;

    float u[16], f[16], fn[16], fn2[16], nu[16];
    #pragma unroll
    for (int j = 0; j < 16; ++j) u[j] = CH_INF;
    ldrow16(f,  Fb + c0);
    ldrow16(fn, Fb + 512 + c0);

    for (int r = 0; r < RB; ++r) {
        if (r < RB - 2) ldrow16(fn2, Fb + (r + 2) * 512 + c0);
        float uL = __shfl_up_sync(FULL, u[15], 1); if (lane == 0)  uL = CH_INF;
        float uR = __shfl_down_sync(FULL, u[0], 1); if (lane == 31) uR = CH_INF;
        #pragma unroll
        for (int j = 0; j < 16; ++j) {
            float left  = (j == 0)  ? uL : u[j - 1];
            float right = (j == 15) ? uR : u[j + 1];
            nu[j] = fminf(fminf(u[j] + CH_A, left + (CH_B - CH_A)),
                          fminf(right + (CH_B + CH_A), f[j]));
        }
        strow16(ub + r * 512 + c0, nu);
        #pragma unroll
        for (int j = 0; j < 16; ++j) { u[j] = nu[j]; f[j] = fn[j]; fn[j] = fn2[j]; }
    }
}

// ============================================================================
// Pass-1 boundary: 512 threads/image, 31 serial steps, group-16 scans.
// ============================================================================
__global__ void k_bnd1() {
    __shared__ float sb_t[2][512], sb_s[2][512];
    const int img = blockIdx.x;
    const int j = threadIdx.x, lane = j & 31;
    const int g = j >> 4;
    const float* base = g_u + img * 262144;
    float* gb = g_bnd + img * NB * 512;
    const float c1 = CH_B - CH_A, c2 = CH_B + CH_A;
    const float c1j = c1 * (float)j, c2j = c2 * (float)j;

    float bb = base[(RB - 1) * 512 + j];
    gb[j] = bb;
    float loc = base[(2 * RB - 1) * 512 + j];

    for (int i = 1; i < NB; ++i) {
        float t = bb - c1j;
        float s = bb + c2j;
        float pre_t = pscan16(t, lane);
        float suf_t = sscan16(t, lane);
        float pre_s = pscan16(s, lane);
        float suf_s = sscan16(s, lane);
        int p = i & 1;
        sb_t[p][j] = suf_t;
        sb_s[p][j] = pre_s;
        float locn = (i + 1 < NB) ? base[((i + 1) * RB + RB - 1) * 512 + j] : 0.0f;
        __syncthreads();
        float suf_t_prev = (g > 0)  ? sb_t[p][j - 16] : CH_INF;
        float pre_s_next = (g < 31) ? sb_s[p][j + 16] : CH_INF;
        float wr = c1j + fminf(suf_t_prev, pre_t);
        float wl = fminf(suf_s, pre_s_next) - c2j;
        float nb = fminf(fminf(wr, wl) + CH_A * (float)RB, loc);
        bb = nb;
        gb[i * 512 + j] = nb;
        loc = locn;
    }
}

// ============================================================================
// FUSED pass-1 fix + emit S (smem) + pass-2 local: 1 warp per (image, block).
// ============================================================================
__global__ void __launch_bounds__(32) k_fix1L2() {
    __shared__ float Ss[RB][512];
    const int img = blockIdx.x >> 5, blk = blockIdx.x & 31;
    const int lane = threadIdx.x, c0 = lane * 16;
    float* ub = g_u + img * 262144 + blk * RB * 512;

    float c2[16];
    #pragma unroll
    for (int j = 0; j < 16; ++j) c2[j] = CH_A * (float)(2 * (c0 + j) - 511);

    if (blk == 0) {
        float out[16];
        #pragma unroll 2
        for (int r = 0; r < RB; ++r) {
            ldrow16(out, ub + r * 512 + c0);
            emitS(&Ss[r][c0], out, c2, lane);
        }
    } else {
        float v[16], nv[16], loc[16], locn[16], locn2[16];
        ldrow16(v, g_bnd + (img * NB + blk - 1) * 512 + c0);
        ldrow16(loc,  ub + c0);
        ldrow16(locn, ub + 512 + c0);
        for (int r = 0; r < RB; ++r) {
            if (r < RB - 2) ldrow16(locn2, ub + (r + 2) * 512 + c0);
            float vL = __shfl_up_sync(FULL, v[15], 1); if (lane == 0)  vL = CH_INF;
            float vR = __shfl_down_sync(FULL, v[0], 1); if (lane == 31) vR = CH_INF;
            #pragma unroll
            for (int j = 0; j < 16; ++j) {
                float left  = (j == 0)  ? vL : v[j - 1];
                float right = (j == 15) ? vR : v[j + 1];
                nv[j] = fminf(v[j] + CH_A, fminf(left + (CH_B - CH_A), right + (CH_B + CH_A)));
            }
            float out[16];
            #pragma unroll
            for (int j = 0; j < 16; ++j) out[j] = fminf(nv[j], loc[j]);
            emitS(&Ss[r][c0], out, c2, lane);
            #pragma unroll
            for (int j = 0; j < 16; ++j) { v[j] = nv[j]; loc[j] = locn[j]; locn[j] = locn2[j]; }
        }
    }
    __syncwarp();

    // pass-2 local (bottom->top), S from shared
    {
        float u[16], f[16], nu[16];
        #pragma unroll
        for (int j = 0; j < 16; ++j) u[j] = CH_INF;
        for (int r = RB - 1; r >= 0; --r) {
            ldrow16(f, &Ss[r][c0]);
            float uL = __shfl_up_sync(FULL, u[15], 1); if (lane == 0)  uL = CH_INF;
            float uR = __shfl_down_sync(FULL, u[0], 1); if (lane == 31) uR = CH_INF;
            #pragma unroll
            for (int j = 0; j < 16; ++j) {
                float left  = (j == 0)  ? uL : u[j - 1];
                float right = (j == 15) ? uR : u[j + 1];
                nu[j] = fminf(fminf(u[j] + CH_A, right + (CH_B - CH_A)),
                              fminf(left + (CH_B + CH_A), f[j]));
            }
            strow16(ub + r * 512 + c0, nu);
            #pragma unroll
            for (int j = 0; j < 16; ++j) u[j] = nu[j];
        }
    }
}

// ============================================================================
// Pass-2 boundary (mirrored slopes), 31 serial steps, group-16 scans.
// ============================================================================
__global__ void k_bnd2() {
    __shared__ float sb_t[2][512], sb_s[2][512];
    const int img = blockIdx.x;
    const int j = threadIdx.x, lane = j & 31;
    const int g = j >> 4;
    const float* base = g_u + img * 262144;
    float* gb = g_bnd + img * NB * 512;
    const float c1 = CH_B - CH_A, c2 = CH_B + CH_A;
    const float c1j = c1 * (float)j, c2j = c2 * (float)j;

    float bb = base[((NB - 1) * RB) * 512 + j];
    gb[(NB - 1) * 512 + j] = bb;
    float loc = base[((NB - 2) * RB) * 512 + j];

    for (int i = NB - 2; i >= 0; --i) {
        float t = bb - c2j;
        float s = bb + c1j;
        float pre_t = pscan16(t, lane);
        float suf_t = sscan16(t, lane);
        float pre_s = pscan16(s, lane);
        float suf_s = sscan16(s, lane);
        int p = i & 1;
        sb_t[p][j] = suf_t;
        sb_s[p][j] = pre_s;
        float locn = (i > 0) ? base[((i - 1) * RB) * 512 + j] : 0.0f;
        __syncthreads();
        float suf_t_prev = (g > 0)  ? sb_t[p][j - 16] : CH_INF;
        float pre_s_next = (g < 31) ? sb_s[p][j + 16] : CH_INF;
        float wr = c2j + fminf(suf_t_prev, pre_t);
        float wl = fminf(suf_s, pre_s_next) - c1j;
        float nb = fminf(fminf(wr, wl) + CH_A * (float)RB, loc);
        bb = nb;
        gb[i * 512 + j] = nb;
        loc = locn;
    }
}

// per-row loss accumulation (16 cols of one row for this lane)
static __device__ __forceinline__ void loss_row(
    const float* __restrict__ pr, unsigned bits, const float* out, const float* co,
    float& s_focal, float& s_i, float& s_p, float& s_t,
    float& s_w, float& s_wd, float& dmx)
{
    float x16[16];
    ldrow16(x16, pr);
    #pragma unroll
    for (int j = 0; j < 16; ++j) {
        float x   = x16[j];
        int   tgi = (bits >> j) & 1;
        float d   = out[j] + co[j];
        dmx = fmaxf(dmx, d);
        float t = (float)tgi;
        float ax = fabsf(x);
        float ee = __expf(-ax);
        float l  = __logf(1.0f + ee);
        float lsp = (x >= 0.f) ? -l : (x - l);
        float lsn = (x >= 0.f) ? (-x - l) : -l;
        float bce = -(t * lsp + (1.f - t) * lsn);
        float r1 = __fdividef(1.0f, 1.0f + ee);
        float p = (x >= 0.f) ? r1 : ee * r1;
        float pt = tgi ? p : (1.f - p);
        float at = tgi ? 0.25f : 0.75f;
        float om = 1.f - pt;
        s_focal += at * om * om * bce;
        s_i += p * t;
        s_p += p;
        s_t += t;
        float w = t * (1.f - p) + (1.f - t) * p;
        s_w  += w;
        s_wd += w * d;
    }
}

// ============================================================================
// FUSED pass-2 fix + ALL losses + dmax. 1 warp per (image, block).
// No g_u store — d rows are consumed in registers. bnd split: S1=Σw, S2=Σwd.
// ============================================================================
__global__ void __launch_bounds__(32) k_fix2L(const float* __restrict__ pred) {
    const int img = blockIdx.x >> 5;
    const int blk = blockIdx.x & 31;
    const int lane = threadIdx.x, c0 = lane * 16;
    const float* ub = g_u + img * 262144 + blk * RB * 512;
    const float* pimg = pred + img * 262144 + blk * RB * 512;
    const unsigned* gmk = g_mask + img * 8192 + blk * RB * 16;

    float co[16];
    #pragma unroll
    for (int j = 0; j < 16; ++j) co[j] = CH_A * (float)(511 - (c0 + j));

    float s_focal = 0.f, s_i = 0.f, s_p = 0.f, s_t = 0.f, s_w = 0.f, s_wd = 0.f;
    float dmx = 0.0f;

    if (blk == NB - 1) {
        float rr[16];
        for (int r = 0; r < RB; ++r) {
            ldrow16(rr, ub + r * 512 + c0);
            unsigned bits = (gmk[r * 16 + (c0 >> 5)] >> (c0 & 31)) & 0xFFFFu;
            loss_row(pimg + r * 512 + c0, bits, rr, co,
                     s_focal, s_i, s_p, s_t, s_w, s_wd, dmx);
        }
    } else {
        float v[16], nv[16], loc[16], locn[16], locn2[16];
        ldrow16(v, g_bnd + (img * NB + blk + 1) * 512 + c0);
        ldrow16(loc,  ub + (RB - 1) * 512 + c0);
        ldrow16(locn, ub + (RB - 2) * 512 + c0);

        for (int r = RB - 1; r >= 0; --r) {
            if (r > 1) ldrow16(locn2, ub + (r - 2) * 512 + c0);
            float vL = __shfl_up_sync(FULL, v[15], 1); if (lane == 0)  vL = CH_INF;
            float vR = __shfl_down_sync(FULL, v[0], 1); if (lane == 31) vR = CH_INF;
            #pragma unroll
            for (int j = 0; j < 16; ++j) {
                float left  = (j == 0)  ? vL : v[j - 1];
                float right = (j == 15) ? vR : v[j + 1];
                nv[j] = fminf(v[j] + CH_A, fminf(right + (CH_B - CH_A), left + (CH_B + CH_A)));
            }
            float out[16];
            #pragma unroll
            for (int j = 0; j < 16; ++j) out[j] = fminf(nv[j], loc[j]);
            unsigned bits = (gmk[r * 16 + (c0 >> 5)] >> (c0 & 31)) & 0xFFFFu;
            loss_row(pimg + r * 512 + c0, bits, out, co,
                     s_focal, s_i, s_p, s_t, s_w, s_wd, dmx);
            #pragma unroll
            for (int j = 0; j < 16; ++j) { v[j] = nv[j]; loc[j] = locn[j]; locn[j] = locn2[j]; }
        }
    }

    // warp reduce 6 sums + 1 max
    #pragma unroll
    for (int o = 16; o >= 1; o >>= 1) {
        s_focal += __shfl_xor_sync(FULL, s_focal, o);
        s_i     += __shfl_xor_sync(FULL, s_i, o);
        s_p     += __shfl_xor_sync(FULL, s_p, o);
        s_t     += __shfl_xor_sync(FULL, s_t, o);
        s_w     += __shfl_xor_sync(FULL, s_w, o);
        s_wd    += __shfl_xor_sync(FULL, s_wd, o);
        dmx = fmaxf(dmx, __shfl_xor_sync(FULL, dmx, o));
    }
    if (lane == 0) {
        atomicAdd(&g_acc[0], s_focal);
        atomicAdd(&g_acc[2 + img], s_i);
        atomicAdd(&g_acc[18 + img], s_p);
        atomicAdd(&g_acc[34 + img], s_t);
        atomicAdd(&g_acc[50 + img], s_w);
        atomicAdd(&g_acc[66 + img], s_wd);
        atomicMax(&g_dmaxb[img], __float_as_int(dmx));
    }
}

// ============================================================================
// Final combine
// ============================================================================
__global__ void k_final(const float* __restrict__ log_vars, float* __restrict__ out) {
    if (threadIdx.x != 0) return;
    const float N = 16.0f * 512.0f * 512.0f;
    float focal = g_acc[0] / N;
    float dsum = 0.f, isum = 0.f, bsum = 0.f;
    #pragma unroll
    for (int b = 0; b < 16; ++b) {
        float I = g_acc[2 + b];
        float T = g_acc[18 + b] + g_acc[34 + b];
        dsum += (2.0f * I + 1e-6f) / (T + 1e-6f);
        isum += (I + 1e-6f) / (T - I + 1e-6f);
        float S1 = g_acc[50 + b], S2 = g_acc[66 + b];
        float mx = __int_as_float(g_dmaxb[b]);
        float inv = (mx > 0.0f) ? (1.0f / fmaxf(mx, 1e-12f)) : 1.0f;
        float dist_part = g_hasfg[b] ? (S2 * inv) : S1;   // hfg: Σw·d/dmax ; else dist=1 → Σw
        bsum += S1 + dist_part;
    }
    float dice = 1.0f - dsum / 16.0f;
    float iou  = 1.0f - isum / 16.0f;
    float bnd  = bsum / N;
    float lv0 = log_vars[0], lv1 = log_vars[1], lv2 = log_vars[2], lv3 = log_vars[3];
    float total = expf(-lv0) * focal + lv0
                + expf(-lv1) * dice  + lv1
                + expf(-lv2) * bnd   + lv2
                + expf(-lv3) * iou   + lv3;
    out[0] = total; out[1] = focal; out[2] = dice; out[3] = bnd; out[4] = iou;
}

extern "C" void kernel_launch(void* const* d_in, const int* in_sizes, int n_in,
                              void* d_out, int out_size) {
    const float* pred     = (const float*)d_in[0];
    const float* log_vars = (const float*)d_in[2];
    float* out = (float*)d_out;

    const size_t smem_seeds = 4 * 8192 * sizeof(unsigned);
    cudaFuncSetAttribute(k_seedsF, cudaFuncAttributeMaxDynamicSharedMemorySize, (int)smem_seeds);

    k_seedsF<<<16, 512, smem_seeds>>>((const int*)d_in[1]);
    k_local1<<<16 * NB, 32>>>();
    k_bnd1<<<16, 512>>>();
    k_fix1L2<<<16 * NB, 32>>>();
    k_bnd2<<<16, 512>>>();
    k_fix2L<<<16 * NB, 32>>>(pred);
    k_final<<<1, 32>>>(log_vars, out);
}

// round 16
// speedup vs baseline: 2.6581x; 1.2653x over previous
#include <cuda_runtime.h>
#include <math.h>

#define FULL 0xFFFFFFFFu

#define CH_A 0.955f
#define CH_B 1.3693f
#define CH_INF 1e6f

#define RB 16            // rows per block
#define NB 32            // blocks per image

// ---- device scratch (no allocation allowed) ----
__device__ float    g_u[16 * 512 * 512];   // pass-1 local rows, then pass-2 rows
__device__ float    g_F[16 * 512 * 512];   // pass-1 seed prefix term
__device__ float    g_bnd[16 * NB * 512];  // corrected block-boundary rows
__device__ unsigned g_mask[16 * 8192];     // raw target bitboard
__device__ int      g_dmaxb[16];           // per-image max distance (float bits)
__device__ int      g_hasfg[16];
// [0]=focal | [2..17]=inter | [18..33]=psum | [34..49]=tsum | [50..65]=S1 | [66..81]=S2
__device__ float    g_acc[82];

// ============================================================================
// k_pack: wide bit-pack of target -> g_mask. 128 CTAs x 256 threads.
// Each warp packs 8 rows (4 column-passes of 128 cols). Also zeroes accums.
// ============================================================================
__global__ void k_pack(const int* __restrict__ target) {
    const int tid  = threadIdx.x;
    const int lane = tid & 31;
    const int warp = tid >> 5;                 // 0..7
    if (blockIdx.x == 0) {
        if (tid < 82) g_acc[tid] = 0.0f;
        if (tid < 16) g_dmaxb[tid] = 0;
    }
    const int gw   = blockIdx.x * 8 + warp;    // global warp 0..1023
    const int row0 = gw * 8;                   // 8 rows per warp (8192 rows total)

    const int grp = lane >> 3;                 // 0..3 (word within pass)
    const int sub = lane & 7;
    const unsigned gm = 0xFFu << (grp * 8);

    #pragma unroll
    for (int rr = 0; rr < 8; ++rr) {
        int row = row0 + rr;                   // global row = img*512 + r
        #pragma unroll
        for (int ps = 0; ps < 4; ++ps) {
            int col = ps * 128 + lane * 4;
            int4 v4 = *(const int4*)(target + row * 512 + col);
            unsigned nib = (v4.x > 0 ? 1u : 0u) | (v4.y > 0 ? 2u : 0u)
                         | (v4.z > 0 ? 4u : 0u) | (v4.w > 0 ? 8u : 0u);
            unsigned word = __reduce_or_sync(gm, nib << (sub * 4));
            if (sub == 0) g_mask[row * 16 + ps * 4 + grp] = word;
        }
    }
}

// ============================================================================
// k_seedF: morphology + F from g_mask. One CTA per image, 512 threads.
// ============================================================================
__global__ void k_seedF() {
    extern __shared__ unsigned char smem_raw[];
    unsigned* maskb = (unsigned*)smem_raw;   // 8192 words
    unsigned* hdb   = maskb + 8192;          // later reused as carry table C
    unsigned* heb   = hdb + 8192;
    unsigned* bdb   = heb + 8192;

    const int img  = blockIdx.x;
    const int tid  = threadIdx.x;
    const unsigned* gmk = g_mask + img * 8192;

    // load bitboard; compute has_fg
    unsigned anyfg = 0;
    #pragma unroll
    for (int k = 0; k < 16; ++k) {
        unsigned w = gmk[tid + k * 512];
        maskb[tid + k * 512] = w;
        anyfg |= w;
    }
    int has_fg = __syncthreads_or(anyfg != 0);

    // horizontal dilate/erode
    #pragma unroll
    for (int k = 0; k < 16; ++k) {
        int i = tid + k * 512;
        int w = i & 15;
        unsigned cw  = maskb[i];
        unsigned pw  = (w > 0)  ? maskb[i - 1] : 0u;
        unsigned nw_ = (w < 15) ? maskb[i + 1] : 0u;
        unsigned ld = (cw << 1) | (pw >> 31);
        unsigned rd = (cw >> 1) | (nw_ << 31);
        hdb[i] = cw | ld | rd;
        unsigned le = (cw << 1) | ((w == 0)  ? 1u          : (pw >> 31));
        unsigned re = (cw >> 1) | ((w == 15) ? 0x80000000u : (nw_ << 31));
        heb[i] = cw & le & re;
    }
    __syncthreads();

    // vertical combine -> boundary
    unsigned anyb = 0;
    #pragma unroll
    for (int k = 0; k < 16; ++k) {
        int i = tid + k * 512;
        int r = i >> 4;
        unsigned dil = hdb[i];
        unsigned ero = heb[i];
        if (r > 0)   { dil |= hdb[i - 16]; ero &= heb[i - 16]; }
        if (r < 511) { dil |= hdb[i + 16]; ero &= heb[i + 16]; }
        unsigned bd = dil & ~ero;
        bdb[i] = bd;
        anyb |= bd;
    }
    int has_b = __syncthreads_or(anyb != 0);

    // seed words -> maskb
    #pragma unroll
    for (int k = 0; k < 16; ++k) {
        int i = tid + k * 512;
        maskb[i] = has_b ? bdb[i] : ~maskb[i];
    }
    __syncthreads();

    // per-row carry table (thread = row)
    int* C = (int*)hdb;
    {
        int cur = -1;
        #pragma unroll
        for (int w = 0; w < 16; ++w) {
            C[tid * 16 + w] = cur;
            unsigned word = maskb[tid * 16 + w];
            if (word) cur = w * 32 + 31 - __clz(word);
        }
    }
    __syncthreads();

    // write F (float4-coalesced)
    float* Fimg = g_F + img * 262144;
    for (int qq = tid; qq < 65536; qq += 512) {
        int idx = qq * 4;
        int r = idx >> 9, j0 = idx & 511;
        int w = j0 >> 5;
        unsigned word = maskb[r * 16 + w];
        int carry = C[r * 16 + w];
        float4 o;
        #pragma unroll
        for (int e = 0; e < 4; ++e) {
            int j = j0 + e, b = j & 31;
            unsigned lb = word & (0xFFFFFFFFu >> (31 - b));
            int id = lb ? (w * 32 + 31 - __clz(lb)) : carry;
            (&o.x)[e] = (id >= 0) ? (-CH_A * (float)id) : CH_INF;
        }
        *(float4*)(Fimg + idx) = o;
    }
    if (tid == 0) g_hasfg[img] = has_fg;
}

static __device__ __forceinline__ void ldrow16(float* d, const float* p) {
    float4 a = *(const float4*)(p);
    float4 b = *(const float4*)(p + 4);
    float4 c = *(const float4*)(p + 8);
    float4 e = *(const float4*)(p + 12);
    d[0]=a.x; d[1]=a.y; d[2]=a.z; d[3]=a.w;
    d[4]=b.x; d[5]=b.y; d[6]=b.z; d[7]=b.w;
    d[8]=c.x; d[9]=c.y; d[10]=c.z; d[11]=c.w;
    d[12]=e.x; d[13]=e.y; d[14]=e.z; d[15]=e.w;
}
static __device__ __forceinline__ void strow16(float* p, const float* d) {
    *(float4*)(p)      = make_float4(d[0], d[1], d[2], d[3]);
    *(float4*)(p + 4)  = make_float4(d[4], d[5], d[6], d[7]);
    *(float4*)(p + 8)  = make_float4(d[8], d[9], d[10], d[11]);
    *(float4*)(p + 12) = make_float4(d[12], d[13], d[14], d[15]);
}

// 16-lane group scans (inclusive)
static __device__ __forceinline__ float pscan16(float x, int lane) {
    #pragma unroll
    for (int o = 1; o < 16; o <<= 1) {
        float v = __shfl_up_sync(FULL, x, o);
        if ((lane & 15) >= o) x = fminf(x, v);
    }
    return x;
}
static __device__ __forceinline__ float sscan16(float x, int lane) {
    #pragma unroll
    for (int o = 1; o < 16; o <<= 1) {
        float v = __shfl_down_sync(FULL, x, o);
        if ((lane & 15) + o < 16) x = fminf(x, v);
    }
    return x;
}
static __device__ __forceinline__ float sscan_min(float x, int lane) {
    #pragma unroll
    for (int o = 1; o < 32; o <<= 1) {
        float v = __shfl_down_sync(FULL, x, o);
        if (lane + o < 32) x = fminf(x, v);
    }
    return x;
}

// Suffix-scan a row into S (shared): S[j] = min_{k>=j}(out[k] + c2[k])
static __device__ __forceinline__ void emitS(float* Sp, const float* out, const float* c2, int lane) {
    float nxc[16], s[16];
    #pragma unroll
    for (int j = 0; j < 16; ++j) nxc[j] = out[j] + c2[j];
    s[15] = nxc[15];
    #pragma unroll
    for (int j = 14; j >= 0; --j) s[j] = fminf(s[j + 1], nxc[j]);
    float inc = sscan_min(s[0], lane);
    float exc = __shfl_down_sync(FULL, inc, 1);
    if (lane == 31) exc = CH_INF;
    #pragma unroll
    for (int k = 0; k < 4; ++k)
        *(float4*)(Sp + 4 * k) = make_float4(fminf(s[4*k], exc), fminf(s[4*k+1], exc),
                                             fminf(s[4*k+2], exc), fminf(s[4*k+3], exc));
}

// ============================================================================
// Pass-1 local: 1 warp per (image, block). Depth-3 prefetch of F.
// ============================================================================
__global__ void __launch_bounds__(32, 1) k_local1() {
    const int img = blockIdx.x >> 5, blk = blockIdx.x & 31;
    const int lane = threadIdx.x, c0 = lane * 16;
    const float* Fb = g_F + img * 262144 + blk * RB * 512;
    float* ub = g_u + img * 262144 + blk * RB * 512;

    float u[16], f[16], fn[16], fn2[16], fn3[16], nu[16];
    #pragma unroll
    for (int j = 0; j < 16; ++j) u[j] = CH_INF;
    ldrow16(f,   Fb + c0);
    ldrow16(fn,  Fb + 512 + c0);
    ldrow16(fn2, Fb + 1024 + c0);

    for (int r = 0; r < RB; ++r) {
        if (r < RB - 3) ldrow16(fn3, Fb + (r + 3) * 512 + c0);
        float uL = __shfl_up_sync(FULL, u[15], 1); if (lane == 0)  uL = CH_INF;
        float uR = __shfl_down_sync(FULL, u[0], 1); if (lane == 31) uR = CH_INF;
        #pragma unroll
        for (int j = 0; j < 16; ++j) {
            float left  = (j == 0)  ? uL : u[j - 1];
            float right = (j == 15) ? uR : u[j + 1];
            nu[j] = fminf(fminf(u[j] + CH_A, left + (CH_B - CH_A)),
                          fminf(right + (CH_B + CH_A), f[j]));
        }
        strow16(ub + r * 512 + c0, nu);
        #pragma unroll
        for (int j = 0; j < 16; ++j) { u[j] = nu[j]; f[j] = fn[j]; fn[j] = fn2[j]; fn2[j] = fn3[j]; }
    }
}

// ============================================================================
// Pass-1 boundary: 512 threads/image, 31 serial steps, group-16 scans.
// ============================================================================
__global__ void k_bnd1() {
    __shared__ float sb_t[2][512], sb_s[2][512];
    const int img = blockIdx.x;
    const int j = threadIdx.x, lane = j & 31;
    const int g = j >> 4;
    const float* base = g_u + img * 262144;
    float* gb = g_bnd + img * NB * 512;
    const float c1 = CH_B - CH_A, c2 = CH_B + CH_A;
    const float c1j = c1 * (float)j, c2j = c2 * (float)j;

    float bb = base[(RB - 1) * 512 + j];
    gb[j] = bb;
    float loc = base[(2 * RB - 1) * 512 + j];

    for (int i = 1; i < NB; ++i) {
        float t = bb - c1j;
        float s = bb + c2j;
        float pre_t = pscan16(t, lane);
        float suf_t = sscan16(t, lane);
        float pre_s = pscan16(s, lane);
        float suf_s = sscan16(s, lane);
        int p = i & 1;
        sb_t[p][j] = suf_t;
        sb_s[p][j] = pre_s;
        float locn = (i + 1 < NB) ? base[((i + 1) * RB + RB - 1) * 512 + j] : 0.0f;
        __syncthreads();
        float suf_t_prev = (g > 0)  ? sb_t[p][j - 16] : CH_INF;
        float pre_s_next = (g < 31) ? sb_s[p][j + 16] : CH_INF;
        float wr = c1j + fminf(suf_t_prev, pre_t);
        float wl = fminf(suf_s, pre_s_next) - c2j;
        float nb = fminf(fminf(wr, wl) + CH_A * (float)RB, loc);
        bb = nb;
        gb[i * 512 + j] = nb;
        loc = locn;
    }
}

// ============================================================================
// FUSED pass-1 fix + emit S (smem) + pass-2 local. Depth-3 prefetch.
// ============================================================================
__global__ void __launch_bounds__(32) k_fix1L2() {
    __shared__ float Ss[RB][512];
    const int img = blockIdx.x >> 5, blk = blockIdx.x & 31;
    const int lane = threadIdx.x, c0 = lane * 16;
    float* ub = g_u + img * 262144 + blk * RB * 512;

    float c2[16];
    #pragma unroll
    for (int j = 0; j < 16; ++j) c2[j] = CH_A * (float)(2 * (c0 + j) - 511);

    if (blk == 0) {
        float out[16];
        #pragma unroll 2
        for (int r = 0; r < RB; ++r) {
            ldrow16(out, ub + r * 512 + c0);
            emitS(&Ss[r][c0], out, c2, lane);
        }
    } else {
        float v[16], nv[16], loc[16], locn[16], locn2[16], locn3[16];
        ldrow16(v, g_bnd + (img * NB + blk - 1) * 512 + c0);
        ldrow16(loc,   ub + c0);
        ldrow16(locn,  ub + 512 + c0);
        ldrow16(locn2, ub + 1024 + c0);
        for (int r = 0; r < RB; ++r) {
            if (r < RB - 3) ldrow16(locn3, ub + (r + 3) * 512 + c0);
            float vL = __shfl_up_sync(FULL, v[15], 1); if (lane == 0)  vL = CH_INF;
            float vR = __shfl_down_sync(FULL, v[0], 1); if (lane == 31) vR = CH_INF;
            #pragma unroll
            for (int j = 0; j < 16; ++j) {
                float left  = (j == 0)  ? vL : v[j - 1];
                float right = (j == 15) ? vR : v[j + 1];
                nv[j] = fminf(v[j] + CH_A, fminf(left + (CH_B - CH_A), right + (CH_B + CH_A)));
            }
            float out[16];
            #pragma unroll
            for (int j = 0; j < 16; ++j) out[j] = fminf(nv[j], loc[j]);
            emitS(&Ss[r][c0], out, c2, lane);
            #pragma unroll
            for (int j = 0; j < 16; ++j) { v[j] = nv[j]; loc[j] = locn[j]; locn[j] = locn2[j]; locn2[j] = locn3[j]; }
        }
    }
    __syncwarp();

    // pass-2 local (bottom->top), S from shared
    {
        float u[16], f[16], nu[16];
        #pragma unroll
        for (int j = 0; j < 16; ++j) u[j] = CH_INF;
        for (int r = RB - 1; r >= 0; --r) {
            ldrow16(f, &Ss[r][c0]);
            float uL = __shfl_up_sync(FULL, u[15], 1); if (lane == 0)  uL = CH_INF;
            float uR = __shfl_down_sync(FULL, u[0], 1); if (lane == 31) uR = CH_INF;
            #pragma unroll
            for (int j = 0; j < 16; ++j) {
                float left  = (j == 0)  ? uL : u[j - 1];
                float right = (j == 15) ? uR : u[j + 1];
                nu[j] = fminf(fminf(u[j] + CH_A, right + (CH_B - CH_A)),
                              fminf(left + (CH_B + CH_A), f[j]));
            }
            strow16(ub + r * 512 + c0, nu);
            #pragma unroll
            for (int j = 0; j < 16; ++j) u[j] = nu[j];
        }
    }
}

// ============================================================================
// Pass-2 boundary (mirrored slopes), 31 serial steps, group-16 scans.
// ============================================================================
__global__ void k_bnd2() {
    __shared__ float sb_t[2][512], sb_s[2][512];
    const int img = blockIdx.x;
    const int j = threadIdx.x, lane = j & 31;
    const int g = j >> 4;
    const float* base = g_u + img * 262144;
    float* gb = g_bnd + img * NB * 512;
    const float c1 = CH_B - CH_A, c2 = CH_B + CH_A;
    const float c1j = c1 * (float)j, c2j = c2 * (float)j;

    float bb = base[((NB - 1) * RB) * 512 + j];
    gb[(NB - 1) * 512 + j] = bb;
    float loc = base[((NB - 2) * RB) * 512 + j];

    for (int i = NB - 2; i >= 0; --i) {
        float t = bb - c2j;
        float s = bb + c1j;
        float pre_t = pscan16(t, lane);
        float suf_t = sscan16(t, lane);
        float pre_s = pscan16(s, lane);
        float suf_s = sscan16(s, lane);
        int p = i & 1;
        sb_t[p][j] = suf_t;
        sb_s[p][j] = pre_s;
        float locn = (i > 0) ? base[((i - 1) * RB) * 512 + j] : 0.0f;
        __syncthreads();
        float suf_t_prev = (g > 0)  ? sb_t[p][j - 16] : CH_INF;
        float pre_s_next = (g < 31) ? sb_s[p][j + 16] : CH_INF;
        float wr = c2j + fminf(suf_t_prev, pre_t);
        float wl = fminf(suf_s, pre_s_next) - c1j;
        float nb = fminf(fminf(wr, wl) + CH_A * (float)RB, loc);
        bb = nb;
        gb[i * 512 + j] = nb;
        loc = locn;
    }
}

// per-row loss accumulation (16 cols of one row for this lane)
static __device__ __forceinline__ void loss_row(
    const float* __restrict__ pr, unsigned bits, const float* out, const float* co,
    float& s_focal, float& s_i, float& s_p, float& s_t,
    float& s_w, float& s_wd, float& dmx)
{
    float x16[16];
    ldrow16(x16, pr);
    #pragma unroll
    for (int j = 0; j < 16; ++j) {
        float x   = x16[j];
        int   tgi = (bits >> j) & 1;
        float d   = out[j] + co[j];
        dmx = fmaxf(dmx, d);
        float t = (float)tgi;
        float ax = fabsf(x);
        float ee = __expf(-ax);
        float l  = __logf(1.0f + ee);
        float lsp = (x >= 0.f) ? -l : (x - l);
        float lsn = (x >= 0.f) ? (-x - l) : -l;
        float bce = -(t * lsp + (1.f - t) * lsn);
        float r1 = __fdividef(1.0f, 1.0f + ee);
        float p = (x >= 0.f) ? r1 : ee * r1;
        float pt = tgi ? p : (1.f - p);
        float at = tgi ? 0.25f : 0.75f;
        float om = 1.f - pt;
        s_focal += at * om * om * bce;
        s_i += p * t;
        s_p += p;
        s_t += t;
        float w = t * (1.f - p) + (1.f - t) * p;
        s_w  += w;
        s_wd += w * d;
    }
}

// ============================================================================
// FUSED pass-2 fix + ALL losses + dmax. Depth-3 prefetch. No g_u store.
// ============================================================================
__global__ void __launch_bounds__(32) k_fix2L(const float* __restrict__ pred) {
    const int img = blockIdx.x >> 5;
    const int blk = blockIdx.x & 31;
    const int lane = threadIdx.x, c0 = lane * 16;
    const float* ub = g_u + img * 262144 + blk * RB * 512;
    const float* pimg = pred + img * 262144 + blk * RB * 512;
    const unsigned* gmk = g_mask + img * 8192 + blk * RB * 16;

    float co[16];
    #pragma unroll
    for (int j = 0; j < 16; ++j) co[j] = CH_A * (float)(511 - (c0 + j));

    float s_focal = 0.f, s_i = 0.f, s_p = 0.f, s_t = 0.f, s_w = 0.f, s_wd = 0.f;
    float dmx = 0.0f;

    if (blk == NB - 1) {
        float rr[16];
        for (int r = 0; r < RB; ++r) {
            ldrow16(rr, ub + r * 512 + c0);
            unsigned bits = (gmk[r * 16 + (c0 >> 5)] >> (c0 & 31)) & 0xFFFFu;
            loss_row(pimg + r * 512 + c0, bits, rr, co,
                     s_focal, s_i, s_p, s_t, s_w, s_wd, dmx);
        }
    } else {
        float v[16], nv[16], loc[16], locn[16], locn2[16], locn3[16];
        ldrow16(v, g_bnd + (img * NB + blk + 1) * 512 + c0);
        ldrow16(loc,   ub + (RB - 1) * 512 + c0);
        ldrow16(locn,  ub + (RB - 2) * 512 + c0);
        ldrow16(locn2, ub + (RB - 3) * 512 + c0);

        for (int r = RB - 1; r >= 0; --r) {
            if (r > 2) ldrow16(locn3, ub + (r - 3) * 512 + c0);
            float vL = __shfl_up_sync(FULL, v[15], 1); if (lane == 0)  vL = CH_INF;
            float vR = __shfl_down_sync(FULL, v[0], 1); if (lane == 31) vR = CH_INF;
            #pragma unroll
            for (int j = 0; j < 16; ++j) {
                float left  = (j == 0)  ? vL : v[j - 1];
                float right = (j == 15) ? vR : v[j + 1];
                nv[j] = fminf(v[j] + CH_A, fminf(right + (CH_B - CH_A), left + (CH_B + CH_A)));
            }
            float out[16];
            #pragma unroll
            for (int j = 0; j < 16; ++j) out[j] = fminf(nv[j], loc[j]);
            unsigned bits = (gmk[r * 16 + (c0 >> 5)] >> (c0 & 31)) & 0xFFFFu;
            loss_row(pimg + r * 512 + c0, bits, out, co,
                     s_focal, s_i, s_p, s_t, s_w, s_wd, dmx);
            #pragma unroll
            for (int j = 0; j < 16; ++j) { v[j] = nv[j]; loc[j] = locn[j]; locn[j] = locn2[j]; locn2[j] = locn3[j]; }
        }
    }

    // warp reduce 6 sums + 1 max
    #pragma unroll
    for (int o = 16; o >= 1; o >>= 1) {
        s_focal += __shfl_xor_sync(FULL, s_focal, o);
        s_i     += __shfl_xor_sync(FULL, s_i, o);
        s_p     += __shfl_xor_sync(FULL, s_p, o);
        s_t     += __shfl_xor_sync(FULL, s_t, o);
        s_w     += __shfl_xor_sync(FULL, s_w, o);
        s_wd    += __shfl_xor_sync(FULL, s_wd, o);
        dmx = fmaxf(dmx, __shfl_xor_sync(FULL, dmx, o));
    }
    if (lane == 0) {
        atomicAdd(&g_acc[0], s_focal);
        atomicAdd(&g_acc[2 + img], s_i);
        atomicAdd(&g_acc[18 + img], s_p);
        atomicAdd(&g_acc[34 + img], s_t);
        atomicAdd(&g_acc[50 + img], s_w);
        atomicAdd(&g_acc[66 + img], s_wd);
        atomicMax(&g_dmaxb[img], __float_as_int(dmx));
    }
}

// ============================================================================
// Final combine
// ============================================================================
__global__ void k_final(const float* __restrict__ log_vars, float* __restrict__ out) {
    if (threadIdx.x != 0) return;
    const float N = 16.0f * 512.0f * 512.0f;
    float focal = g_acc[0] / N;
    float dsum = 0.f, isum = 0.f, bsum = 0.f;
    #pragma unroll
    for (int b = 0; b < 16; ++b) {
        float I = g_acc[2 + b];
        float T = g_acc[18 + b] + g_acc[34 + b];
        dsum += (2.0f * I + 1e-6f) / (T + 1e-6f);
        isum += (I + 1e-6f) / (T - I + 1e-6f);
        float S1 = g_acc[50 + b], S2 = g_acc[66 + b];
        float mx = __int_as_float(g_dmaxb[b]);
        float inv = (mx > 0.0f) ? (1.0f / fmaxf(mx, 1e-12f)) : 1.0f;
        float dist_part = g_hasfg[b] ? (S2 * inv) : S1;
        bsum += S1 + dist_part;
    }
    float dice = 1.0f - dsum / 16.0f;
    float iou  = 1.0f - isum / 16.0f;
    float bnd  = bsum / N;
    float lv0 = log_vars[0], lv1 = log_vars[1], lv2 = log_vars[2], lv3 = log_vars[3];
    float total = expf(-lv0) * focal + lv0
                + expf(-lv1) * dice  + lv1
                + expf(-lv2) * bnd   + lv2
                + expf(-lv3) * iou   + lv3;
    out[0] = total; out[1] = focal; out[2] = dice; out[3] = bnd; out[4] = iou;
}

extern "C" void kernel_launch(void* const* d_in, const int* in_sizes, int n_in,
                              void* d_out, int out_size) {
    const float* pred     = (const float*)d_in[0];
    const float* log_vars = (const float*)d_in[2];
    float* out = (float*)d_out;

    const size_t smem_seed = 4 * 8192 * sizeof(unsigned);
    cudaFuncSetAttribute(k_seedF, cudaFuncAttributeMaxDynamicSharedMemorySize, (int)smem_seed);

    k_pack<<<128, 256>>>((const int*)d_in[1]);
    k_seedF<<<16, 512, smem_seed>>>();
    k_local1<<<16 * NB, 32>>>();
    k_bnd1<<<16, 512>>>();
    k_fix1L2<<<16 * NB, 32>>>();
    k_bnd2<<<16, 512>>>();
    k_fix2L<<<16 * NB, 32>>>(pred);
    k_final<<<1, 32>>>(log_vars, out);
}